// round 1
// baseline (speedup 1.0000x reference)
#include <cuda_runtime.h>
#include <math.h>

// Problem constants
#define S_LEN   2048
#define D_MODEL 4096
#define NH      32
#define NG      8
#define HDIM    128
#define QKV_N   6144          // D + 2*G*HD
#define V_OFF   5120          // D + G*HD

// Scratch (device globals; no allocation allowed)
__device__ float g_qkv[(size_t)S_LEN * QKV_N];        // 50.3 MB
__device__ float g_q  [(size_t)S_LEN * D_MODEL];      // 33.6 MB
__device__ float g_k  [(size_t)S_LEN * NG * HDIM];    //  8.4 MB
__device__ float g_att[(size_t)S_LEN * D_MODEL];      // 33.6 MB

// ---------------------------------------------------------------------------
// GEMM (NT): C[M,N] = A[M,K] * B[N,K]^T     (A, B row-major, K contiguous)
// 128x128x16 block tile, 256 threads, 8x8 microtile with split fragments.
// ---------------------------------------------------------------------------
#define GBM 128
#define GBN 128
#define GBK 16
#define GLD 132   // padded lead dim for [k][m] tiles

__global__ __launch_bounds__(256, 2)
void gemm_nt_kernel(const float* __restrict__ A, const float* __restrict__ B,
                    float* __restrict__ C, int M, int N, int K)
{
    __shared__ float As[GBK][GLD];
    __shared__ float Bs[GBK][GLD];

    const int tid = threadIdx.x;
    const int tx  = tid & 15;
    const int ty  = tid >> 4;
    const int bm  = blockIdx.y * GBM;
    const int bn  = blockIdx.x * GBN;

    float acc[8][8];
#pragma unroll
    for (int i = 0; i < 8; ++i)
#pragma unroll
        for (int j = 0; j < 8; ++j) acc[i][j] = 0.0f;

    const int lr = tid >> 2;          // 0..63
    const int lc = (tid & 3) << 2;    // 0,4,8,12
    const float* Ap = A + (size_t)(bm + lr) * K + lc;
    const float* Bp = B + (size_t)(bn + lr) * K + lc;

    for (int k0 = 0; k0 < K; k0 += GBK) {
#pragma unroll
        for (int r = 0; r < 2; ++r) {
            float4 va = *(const float4*)(Ap + (size_t)r * 64 * K + k0);
            float4 vb = *(const float4*)(Bp + (size_t)r * 64 * K + k0);
            int row = lr + r * 64;
            As[lc + 0][row] = va.x; As[lc + 1][row] = va.y;
            As[lc + 2][row] = va.z; As[lc + 3][row] = va.w;
            Bs[lc + 0][row] = vb.x; Bs[lc + 1][row] = vb.y;
            Bs[lc + 2][row] = vb.z; Bs[lc + 3][row] = vb.w;
        }
        __syncthreads();
#pragma unroll
        for (int k = 0; k < GBK; ++k) {
            float4 a0 = *(const float4*)&As[k][ty * 4];
            float4 a1 = *(const float4*)&As[k][64 + ty * 4];
            float4 b0 = *(const float4*)&Bs[k][tx * 4];
            float4 b1 = *(const float4*)&Bs[k][64 + tx * 4];
            float a[8] = {a0.x, a0.y, a0.z, a0.w, a1.x, a1.y, a1.z, a1.w};
            float b[8] = {b0.x, b0.y, b0.z, b0.w, b1.x, b1.y, b1.z, b1.w};
#pragma unroll
            for (int i = 0; i < 8; ++i)
#pragma unroll
                for (int j = 0; j < 8; ++j)
                    acc[i][j] = fmaf(a[i], b[j], acc[i][j]);
        }
        __syncthreads();
    }

#pragma unroll
    for (int rh = 0; rh < 2; ++rh)
#pragma unroll
        for (int i = 0; i < 4; ++i) {
            int row = bm + rh * 64 + ty * 4 + i;
#pragma unroll
            for (int ch = 0; ch < 2; ++ch) {
                float4 v = make_float4(acc[rh * 4 + i][ch * 4 + 0],
                                       acc[rh * 4 + i][ch * 4 + 1],
                                       acc[rh * 4 + i][ch * 4 + 2],
                                       acc[rh * 4 + i][ch * 4 + 3]);
                *(float4*)&C[(size_t)row * N + bn + ch * 64 + tx * 4] = v;
            }
        }
}

// ---------------------------------------------------------------------------
// RMSNorm + RoPE. One block per (s, head). heads 0..31 = Q, 32..39 = K.
// ---------------------------------------------------------------------------
__global__ void rmsrope_kernel(const float* __restrict__ qw,
                               const float* __restrict__ kw)
{
    const int s  = blockIdx.x;
    const int hh = blockIdx.y;
    const int d  = threadIdx.x;            // 0..127
    const bool isq = hh < NH;

    const float* src = isq ? (g_qkv + (size_t)s * QKV_N + hh * HDIM)
                           : (g_qkv + (size_t)s * QKV_N + D_MODEL + (hh - NH) * HDIM);
    float w = isq ? qw[d] : kw[d];
    float v = src[d];

    float ss = v * v;
#pragma unroll
    for (int off = 16; off; off >>= 1)
        ss += __shfl_xor_sync(0xffffffffu, ss, off);
    __shared__ float red[4];
    if ((d & 31) == 0) red[d >> 5] = ss;
    __syncthreads();
    float tot = red[0] + red[1] + red[2] + red[3];
    float rms = rsqrtf(tot * (1.0f / HDIM) + 1e-5f);
    float xn  = v * rms * w;

    // RoPE (replicate reference fp32 math)
    int   i    = d >> 1;
    float freq = 1.0f / powf(1000000.0f, (float)(2 * i) * (1.0f / HDIM));
    float ang  = (float)s * freq;
    float c, sn;
    sincosf(ang, &sn, &c);
    float partner = __shfl_xor_sync(0xffffffffu, xn, 1);
    float out = (d & 1) ? (partner * sn + xn * c)    // odd:  a*sin + b*cos
                        : (xn * c - partner * sn);   // even: a*cos - b*sin

    if (isq) g_q[(size_t)s * D_MODEL + hh * HDIM + d] = out;
    else     g_k[(size_t)s * (NG * HDIM) + (hh - NH) * HDIM + d] = out;
}

// ---------------------------------------------------------------------------
// Flash attention (fp32, causal, GQA). BM=BN=64, 256 threads, 4x4 microtile.
// Q,K staged transposed [d][row] with XOR swizzle (conflict-free fragments).
// V row-major [t][d]; P row-major [row][t].
// smem: Qt 32K + Kt 32K + Vs 32K + Ps 16K = 112 KB dynamic -> 2 CTA/SM.
// ---------------------------------------------------------------------------
#define ATT_SMEM ((3 * 128 * 64 + 64 * 64) * sizeof(float))

__global__ __launch_bounds__(256, 2)
void attn_kernel()
{
    extern __shared__ float sm[];
    float* Qt = sm;                    // 128 x 64 (swizzled words)
    float* Kt = sm + 128 * 64;         // 128 x 64 (swizzled words)
    float* Vs = sm + 2 * 128 * 64;     // 64 x 128 row-major
    float* Ps = sm + 3 * 128 * 64;     // 64 x 64 row-major

    const int tid = threadIdx.x;
    const int tx  = tid & 15;
    const int ty  = tid >> 4;
    const int h   = blockIdx.y;
    const int g   = h >> 2;            // HG = 4
    const int qt  = blockIdx.x;
    const int qs  = qt * 64;

    // --- load Q tile transposed + swizzled (once per block) ---
#pragma unroll
    for (int it = 0; it < 8; ++it) {
        int lin = tid + it * 256;
        int row = lin >> 5;            // 0..63
        int d4  = lin & 31;            // 0..31
        float4 v = *(const float4*)&g_q[(size_t)(qs + row) * D_MODEL + h * HDIM + d4 * 4];
        const float* pv = (const float*)&v;
#pragma unroll
        for (int i = 0; i < 4; ++i) {
            int d = d4 * 4 + i;
            Qt[d * 64 + ((((row >> 2) ^ (d4 & 15)) << 2) | (row & 3))] = pv[i];
        }
    }

    float m[4], l[4], o[4][8];
#pragma unroll
    for (int i = 0; i < 4; ++i) {
        m[i] = -1e30f; l[i] = 0.0f;
#pragma unroll
        for (int j = 0; j < 8; ++j) o[i][j] = 0.0f;
    }

    const float scale = 0.08838834764831845f;  // 1/sqrt(128)

    for (int kt = 0; kt <= qt; ++kt) {
        const int ks = kt * 64;
        // --- load K tile (transposed+swizzled) and V tile (row-major) ---
#pragma unroll
        for (int it = 0; it < 8; ++it) {
            int lin = tid + it * 256;
            int col = lin >> 5;
            int d4  = lin & 31;
            float4 v = *(const float4*)&g_k[(size_t)(ks + col) * (NG * HDIM) + g * HDIM + d4 * 4];
            const float* pv = (const float*)&v;
#pragma unroll
            for (int i = 0; i < 4; ++i) {
                int d = d4 * 4 + i;
                Kt[d * 64 + ((((col >> 2) ^ (d4 & 15)) << 2) | (col & 3))] = pv[i];
            }
            float4 vv = *(const float4*)&g_qkv[(size_t)(ks + col) * QKV_N + V_OFF + g * HDIM + d4 * 4];
            *(float4*)&Vs[col * 128 + d4 * 4] = vv;
        }
        __syncthreads();

        // --- S = Q K^T (64x64 tile, 4x4 per thread) ---
        float sa[4][4];
#pragma unroll
        for (int i = 0; i < 4; ++i)
#pragma unroll
            for (int j = 0; j < 4; ++j) sa[i][j] = 0.0f;

#pragma unroll 8
        for (int d = 0; d < 128; ++d) {
            int key = (d >> 2) & 15;
            float4 a = *(const float4*)&Qt[d * 64 + ((ty ^ key) << 2)];
            float4 b = *(const float4*)&Kt[d * 64 + ((tx ^ key) << 2)];
            const float* av = (const float*)&a;
            const float* bv = (const float*)&b;
#pragma unroll
            for (int i = 0; i < 4; ++i)
#pragma unroll
                for (int j = 0; j < 4; ++j)
                    sa[i][j] = fmaf(av[i], bv[j], sa[i][j]);
        }

        // --- scale + causal mask ---
#pragma unroll
        for (int i = 0; i < 4; ++i) {
            int srow = qs + ty * 4 + i;
#pragma unroll
            for (int j = 0; j < 4; ++j) {
                float v = sa[i][j] * scale;
                if (ks + tx * 4 + j > srow) v = -1e30f;
                sa[i][j] = v;
            }
        }

        // --- online softmax (row groups = 16 lanes sharing ty) ---
#pragma unroll
        for (int i = 0; i < 4; ++i) {
            float rm = fmaxf(fmaxf(sa[i][0], sa[i][1]), fmaxf(sa[i][2], sa[i][3]));
#pragma unroll
            for (int off = 8; off; off >>= 1)
                rm = fmaxf(rm, __shfl_xor_sync(0xffffffffu, rm, off));
            float mnew = fmaxf(m[i], rm);
            float corr = __expf(m[i] - mnew);
            float rs = 0.0f;
#pragma unroll
            for (int j = 0; j < 4; ++j) {
                float p = __expf(sa[i][j] - mnew);
                sa[i][j] = p;
                rs += p;
            }
#pragma unroll
            for (int off = 8; off; off >>= 1)
                rs += __shfl_xor_sync(0xffffffffu, rs, off);
            l[i] = l[i] * corr + rs;
            m[i] = mnew;
#pragma unroll
            for (int j = 0; j < 8; ++j) o[i][j] *= corr;
            *(float4*)&Ps[(ty * 4 + i) * 64 + tx * 4] =
                make_float4(sa[i][0], sa[i][1], sa[i][2], sa[i][3]);
        }
        __syncthreads();

        // --- O += P V  (64x128, thread: 4 rows x {tx*4, 64+tx*4} cols) ---
#pragma unroll 4
        for (int t = 0; t < 64; ++t) {
            float a0 = Ps[(ty * 4 + 0) * 64 + t];
            float a1 = Ps[(ty * 4 + 1) * 64 + t];
            float a2 = Ps[(ty * 4 + 2) * 64 + t];
            float a3 = Ps[(ty * 4 + 3) * 64 + t];
            float4 b0 = *(const float4*)&Vs[t * 128 + tx * 4];
            float4 b1 = *(const float4*)&Vs[t * 128 + 64 + tx * 4];
            const float* b0v = (const float*)&b0;
            const float* b1v = (const float*)&b1;
            float ar[4] = {a0, a1, a2, a3};
#pragma unroll
            for (int i = 0; i < 4; ++i) {
#pragma unroll
                for (int j = 0; j < 4; ++j) o[i][j]     = fmaf(ar[i], b0v[j], o[i][j]);
#pragma unroll
                for (int j = 0; j < 4; ++j) o[i][4 + j] = fmaf(ar[i], b1v[j], o[i][4 + j]);
            }
        }
        __syncthreads();
    }

    // --- epilogue ---
#pragma unroll
    for (int i = 0; i < 4; ++i) {
        float inv = 1.0f / l[i];
        int s = qs + ty * 4 + i;
        float4 v0 = make_float4(o[i][0] * inv, o[i][1] * inv, o[i][2] * inv, o[i][3] * inv);
        float4 v1 = make_float4(o[i][4] * inv, o[i][5] * inv, o[i][6] * inv, o[i][7] * inv);
        *(float4*)&g_att[(size_t)s * D_MODEL + h * HDIM + tx * 4] = v0;
        *(float4*)&g_att[(size_t)s * D_MODEL + h * HDIM + 64 + tx * 4] = v1;
    }
}

// ---------------------------------------------------------------------------
extern "C" void kernel_launch(void* const* d_in, const int* in_sizes, int n_in,
                              void* d_out, int out_size)
{
    const float* x     = (const float*)d_in[0];
    const float* w_qkv = (const float*)d_in[1];
    const float* w_out = (const float*)d_in[2];
    const float* q_ln  = (const float*)d_in[3];
    const float* k_ln  = (const float*)d_in[4];
    float* out = (float*)d_out;

    void *qkv_p, *att_p;
    cudaGetSymbolAddress(&qkv_p, g_qkv);
    cudaGetSymbolAddress(&att_p, g_att);

    // 1) QKV projection: [2048,6144] = x[2048,4096] * w_qkv[6144,4096]^T
    dim3 g1(QKV_N / GBN, S_LEN / GBM);
    gemm_nt_kernel<<<g1, 256>>>(x, w_qkv, (float*)qkv_p, S_LEN, QKV_N, D_MODEL);

    // 2) RMSNorm + RoPE (q -> g_q, k -> g_k)
    rmsrope_kernel<<<dim3(S_LEN, NH + NG), 128>>>(q_ln, k_ln);

    // 3) Flash attention -> g_att
    cudaFuncSetAttribute(attn_kernel, cudaFuncAttributeMaxDynamicSharedMemorySize,
                         (int)ATT_SMEM);
    attn_kernel<<<dim3(S_LEN / 64, NH), 256, ATT_SMEM>>>();

    // 4) Output projection: out[2048,4096] = g_att * w_out[4096,4096]^T
    dim3 g2(D_MODEL / GBN, S_LEN / GBM);
    gemm_nt_kernel<<<g2, 256>>>((const float*)att_p, w_out, out,
                                S_LEN, D_MODEL, D_MODEL);
}

// round 3
// speedup vs baseline: 1.9637x; 1.9637x over previous
#include <cuda_runtime.h>
#include <cuda_bf16.h>
#include <cstdint>
#include <math.h>

// Problem constants
#define S_LEN   2048
#define D_MODEL 4096
#define NH      32
#define NG      8
#define HDIM    128
#define QKV_N   6144          // D + 2*G*HD
#define V_OFF   5120          // D + G*HD

// fp32 scratch
__device__ float g_qkv[(size_t)S_LEN * QKV_N];
__device__ float g_q  [(size_t)S_LEN * D_MODEL];
__device__ float g_k  [(size_t)S_LEN * NG * HDIM];
__device__ float g_att[(size_t)S_LEN * D_MODEL];

// bf16 hi/lo split scratch
__device__ __nv_bfloat16 g_xh [(size_t)S_LEN * D_MODEL];
__device__ __nv_bfloat16 g_xl [(size_t)S_LEN * D_MODEL];
__device__ __nv_bfloat16 g_wqh[(size_t)QKV_N * D_MODEL];
__device__ __nv_bfloat16 g_wql[(size_t)QKV_N * D_MODEL];
__device__ __nv_bfloat16 g_woh[(size_t)D_MODEL * D_MODEL];
__device__ __nv_bfloat16 g_wol[(size_t)D_MODEL * D_MODEL];
__device__ __nv_bfloat16 g_ah [(size_t)S_LEN * D_MODEL];
__device__ __nv_bfloat16 g_al [(size_t)S_LEN * D_MODEL];

// ---------------------------------------------------------------------------
// helpers (portable sm_80+ PTX only — target is sm_100, NOT sm_100a)
// ---------------------------------------------------------------------------
__device__ __forceinline__ uint32_t smem_u32(const void* p) {
    uint32_t a;
    asm("{ .reg .u64 t; cvta.to.shared.u64 t, %1; cvt.u32.u64 %0, t; }"
        : "=r"(a) : "l"(p));
    return a;
}
__device__ __forceinline__ uint32_t sw128(uint32_t x) {
    return x ^ ((x >> 3) & 0x70);
}
__device__ __forceinline__ void cp16(uint32_t saddr, const void* gptr) {
    asm volatile("cp.async.cg.shared.global [%0], [%1], 16;"
                 :: "r"(saddr), "l"(gptr) : "memory");
}
__device__ __forceinline__ void ldmx4(uint32_t* r, uint32_t addr) {
    asm volatile("ldmatrix.sync.aligned.m8n8.x4.shared.b16 {%0,%1,%2,%3}, [%4];"
                 : "=r"(r[0]), "=r"(r[1]), "=r"(r[2]), "=r"(r[3]) : "r"(addr));
}
__device__ __forceinline__ void ldmx2(uint32_t* r, uint32_t addr) {
    asm volatile("ldmatrix.sync.aligned.m8n8.x2.shared.b16 {%0,%1}, [%2];"
                 : "=r"(r[0]), "=r"(r[1]) : "r"(addr));
}
__device__ __forceinline__ void mma16816(float* c, const uint32_t* a,
                                         const uint32_t* b) {
    asm volatile(
        "mma.sync.aligned.m16n8k16.row.col.f32.bf16.bf16.f32 "
        "{%0,%1,%2,%3}, {%4,%5,%6,%7}, {%8,%9}, {%0,%1,%2,%3};"
        : "+f"(c[0]), "+f"(c[1]), "+f"(c[2]), "+f"(c[3])
        : "r"(a[0]), "r"(a[1]), "r"(a[2]), "r"(a[3]), "r"(b[0]), "r"(b[1]));
}

// ---------------------------------------------------------------------------
// fp32 -> bf16 hi/lo split
// ---------------------------------------------------------------------------
__global__ void split_kernel(const float* __restrict__ s,
                             __nv_bfloat16* __restrict__ h,
                             __nv_bfloat16* __restrict__ l, int n4)
{
    int i = blockIdx.x * blockDim.x + threadIdx.x;
    if (i >= n4) return;
    float4 v = ((const float4*)s)[i];
    __nv_bfloat16 h0 = __float2bfloat16(v.x);
    __nv_bfloat16 h1 = __float2bfloat16(v.y);
    __nv_bfloat16 h2 = __float2bfloat16(v.z);
    __nv_bfloat16 h3 = __float2bfloat16(v.w);
    __nv_bfloat16 l0 = __float2bfloat16(v.x - __bfloat162float(h0));
    __nv_bfloat16 l1 = __float2bfloat16(v.y - __bfloat162float(h1));
    __nv_bfloat16 l2 = __float2bfloat16(v.z - __bfloat162float(h2));
    __nv_bfloat16 l3 = __float2bfloat16(v.w - __bfloat162float(h3));
    ushort4 hv, lv;
    hv.x = __bfloat16_as_ushort(h0); hv.y = __bfloat16_as_ushort(h1);
    hv.z = __bfloat16_as_ushort(h2); hv.w = __bfloat16_as_ushort(h3);
    lv.x = __bfloat16_as_ushort(l0); lv.y = __bfloat16_as_ushort(l1);
    lv.z = __bfloat16_as_ushort(l2); lv.w = __bfloat16_as_ushort(l3);
    *(ushort4*)(h + 4 * (size_t)i) = hv;
    *(ushort4*)(l + 4 * (size_t)i) = lv;
}

// ---------------------------------------------------------------------------
// bf16 split GEMM via mma.sync (NT): C[M,N] = (Ah+Al)[M,K] * (Bh+Bl)[N,K]^T
// CTA tile 128x128, 8 warps (2x4), warp tile 64x32, K-chunk 64, 2 cp.async
// stages. Smem stage: Ah|Al|Bh|Bl, each 128 rows x 128B, SW128 swizzled.
// ---------------------------------------------------------------------------
#define BM 128
#define BN 128
#define KC 64
#define STAGE_B  65536              // 4 tiles x 16KB
#define GSMEM    (2 * STAGE_B)      // 128 KB

__global__ __launch_bounds__(256, 1)
void gemm_mma(const __nv_bfloat16* __restrict__ Ah, const __nv_bfloat16* __restrict__ Al,
              const __nv_bfloat16* __restrict__ Bh, const __nv_bfloat16* __restrict__ Bl,
              float* __restrict__ C, int M, int N, int K)
{
    extern __shared__ __align__(1024) char smem[];
    const int tid  = threadIdx.x;
    const int wid  = tid >> 5;
    const int lane = tid & 31;
    const int bn   = blockIdx.x * BN;
    const int bm   = blockIdx.y * BM;
    const uint32_t sb = smem_u32(smem);

    const int mrow0 = (wid & 1) * 64;    // warp M offset
    const int ncol0 = (wid >> 1) * 32;   // warp N offset

    float acc[4][4][4];
#pragma unroll
    for (int mt = 0; mt < 4; ++mt)
#pragma unroll
        for (int nt = 0; nt < 4; ++nt)
#pragma unroll
            for (int r = 0; r < 4; ++r) acc[mt][nt][r] = 0.0f;

    const int nchunks = K / KC;

    // ---- staging: each thread copies 4 x 16B per operand tile ----
    auto stage = [&](int c, int s) {
        const int k0 = c * KC;
        const uint32_t base = sb + (uint32_t)s * STAGE_B;
#pragma unroll
        for (int i = 0; i < 4; ++i) {
            int q   = tid + i * 256;      // 0..1023
            int row = q >> 3;             // 0..127
            int col = q & 7;              // 16B col
            uint32_t soff = sw128((uint32_t)row * 128u + (uint32_t)col * 16u);
            size_t ga = (size_t)(bm + row) * K + k0 + col * 8;
            size_t gb = (size_t)(bn + row) * K + k0 + col * 8;
            cp16(base + soff,          Ah + ga);
            cp16(base + 16384 + soff,  Al + ga);
            cp16(base + 32768 + soff,  Bh + gb);
            cp16(base + 49152 + soff,  Bl + gb);
        }
        asm volatile("cp.async.commit_group;" ::: "memory");
    };

    stage(0, 0);
    if (nchunks > 1) stage(1, 1);

    for (int c = 0; c < nchunks; ++c) {
        const int buf = c & 1;
        if (c + 1 < nchunks)
            asm volatile("cp.async.wait_group 1;" ::: "memory");
        else
            asm volatile("cp.async.wait_group 0;" ::: "memory");
        __syncthreads();

        const uint32_t sAh = sb + (uint32_t)buf * STAGE_B;
        const uint32_t sAl = sAh + 16384;
        const uint32_t sBh = sAh + 32768;
        const uint32_t sBl = sAh + 49152;

#pragma unroll
        for (int kk = 0; kk < 4; ++kk) {
            uint32_t ah[4][4], al[4][4], bh[4][2], bl[4][2];
            const int arow = mrow0 + (lane & 15);
            const int acol = kk * 2 + (lane >> 4);
#pragma unroll
            for (int mt = 0; mt < 4; ++mt) {
                uint32_t off = sw128((uint32_t)(arow + mt * 16) * 128u +
                                     (uint32_t)acol * 16u);
                ldmx4(ah[mt], sAh + off);
                ldmx4(al[mt], sAl + off);
            }
            const int brow = ncol0 + (lane & 7);
            const int bcol = kk * 2 + ((lane >> 3) & 1);
#pragma unroll
            for (int nt = 0; nt < 4; ++nt) {
                uint32_t off = sw128((uint32_t)(brow + nt * 8) * 128u +
                                     (uint32_t)bcol * 16u);
                ldmx2(bh[nt], sBh + off);
                ldmx2(bl[nt], sBl + off);
            }
#pragma unroll
            for (int mt = 0; mt < 4; ++mt)
#pragma unroll
                for (int nt = 0; nt < 4; ++nt) {
                    mma16816(acc[mt][nt], ah[mt], bh[nt]);   // hi*hi
                    mma16816(acc[mt][nt], ah[mt], bl[nt]);   // hi*lo
                    mma16816(acc[mt][nt], al[mt], bh[nt]);   // lo*hi
                }
        }
        __syncthreads();
        if (c + 2 < nchunks) stage(c + 2, buf);
    }

    // ---- epilogue ----
#pragma unroll
    for (int mt = 0; mt < 4; ++mt) {
        int r0 = bm + mrow0 + mt * 16 + (lane >> 2);
#pragma unroll
        for (int nt = 0; nt < 4; ++nt) {
            int cc = bn + ncol0 + nt * 8 + (lane & 3) * 2;
            *(float2*)&C[(size_t)r0 * N + cc] =
                make_float2(acc[mt][nt][0], acc[mt][nt][1]);
            *(float2*)&C[(size_t)(r0 + 8) * N + cc] =
                make_float2(acc[mt][nt][2], acc[mt][nt][3]);
        }
    }
}

// ---------------------------------------------------------------------------
// RMSNorm + RoPE. One block per (s, head). heads 0..31 = Q, 32..39 = K.
// ---------------------------------------------------------------------------
__global__ void rmsrope_kernel(const float* __restrict__ qw,
                               const float* __restrict__ kw)
{
    const int s  = blockIdx.x;
    const int hh = blockIdx.y;
    const int d  = threadIdx.x;            // 0..127
    const bool isq = hh < NH;

    const float* src = isq ? (g_qkv + (size_t)s * QKV_N + hh * HDIM)
                           : (g_qkv + (size_t)s * QKV_N + D_MODEL + (hh - NH) * HDIM);
    float w = isq ? qw[d] : kw[d];
    float v = src[d];

    float ss = v * v;
#pragma unroll
    for (int off = 16; off; off >>= 1)
        ss += __shfl_xor_sync(0xffffffffu, ss, off);
    __shared__ float red[4];
    if ((d & 31) == 0) red[d >> 5] = ss;
    __syncthreads();
    float tot = red[0] + red[1] + red[2] + red[3];
    float rms = rsqrtf(tot * (1.0f / HDIM) + 1e-5f);
    float xn  = v * rms * w;

    int   i    = d >> 1;
    float freq = 1.0f / powf(1000000.0f, (float)(2 * i) * (1.0f / HDIM));
    float ang  = (float)s * freq;
    float c, sn;
    sincosf(ang, &sn, &c);
    float partner = __shfl_xor_sync(0xffffffffu, xn, 1);
    float out = (d & 1) ? (partner * sn + xn * c)
                        : (xn * c - partner * sn);

    if (isq) g_q[(size_t)s * D_MODEL + hh * HDIM + d] = out;
    else     g_k[(size_t)s * (NG * HDIM) + (hh - NH) * HDIM + d] = out;
}

// ---------------------------------------------------------------------------
// Flash attention (fp32, causal, GQA). BM=BN=64, 256 threads, 4x4 microtile.
// ---------------------------------------------------------------------------
#define ATT_SMEM ((3 * 128 * 64 + 64 * 64) * sizeof(float))

__global__ __launch_bounds__(256, 2)
void attn_kernel()
{
    extern __shared__ float sm[];
    float* Qt = sm;
    float* Kt = sm + 128 * 64;
    float* Vs = sm + 2 * 128 * 64;
    float* Ps = sm + 3 * 128 * 64;

    const int tid = threadIdx.x;
    const int tx  = tid & 15;
    const int ty  = tid >> 4;
    const int h   = blockIdx.y;
    const int g   = h >> 2;
    const int qt  = blockIdx.x;
    const int qs  = qt * 64;

#pragma unroll
    for (int it = 0; it < 8; ++it) {
        int lin = tid + it * 256;
        int row = lin >> 5;
        int d4  = lin & 31;
        float4 v = *(const float4*)&g_q[(size_t)(qs + row) * D_MODEL + h * HDIM + d4 * 4];
        const float* pv = (const float*)&v;
#pragma unroll
        for (int i = 0; i < 4; ++i) {
            int d = d4 * 4 + i;
            Qt[d * 64 + ((((row >> 2) ^ (d4 & 15)) << 2) | (row & 3))] = pv[i];
        }
    }

    float m[4], l[4], o[4][8];
#pragma unroll
    for (int i = 0; i < 4; ++i) {
        m[i] = -1e30f; l[i] = 0.0f;
#pragma unroll
        for (int j = 0; j < 8; ++j) o[i][j] = 0.0f;
    }

    const float scale = 0.08838834764831845f;

    for (int kt = 0; kt <= qt; ++kt) {
        const int ks = kt * 64;
#pragma unroll
        for (int it = 0; it < 8; ++it) {
            int lin = tid + it * 256;
            int col = lin >> 5;
            int d4  = lin & 31;
            float4 v = *(const float4*)&g_k[(size_t)(ks + col) * (NG * HDIM) + g * HDIM + d4 * 4];
            const float* pv = (const float*)&v;
#pragma unroll
            for (int i = 0; i < 4; ++i) {
                int d = d4 * 4 + i;
                Kt[d * 64 + ((((col >> 2) ^ (d4 & 15)) << 2) | (col & 3))] = pv[i];
            }
            float4 vv = *(const float4*)&g_qkv[(size_t)(ks + col) * QKV_N + V_OFF + g * HDIM + d4 * 4];
            *(float4*)&Vs[col * 128 + d4 * 4] = vv;
        }
        __syncthreads();

        float sa[4][4];
#pragma unroll
        for (int i = 0; i < 4; ++i)
#pragma unroll
            for (int j = 0; j < 4; ++j) sa[i][j] = 0.0f;

#pragma unroll 8
        for (int d = 0; d < 128; ++d) {
            int key = (d >> 2) & 15;
            float4 a = *(const float4*)&Qt[d * 64 + ((ty ^ key) << 2)];
            float4 b = *(const float4*)&Kt[d * 64 + ((tx ^ key) << 2)];
            const float* av = (const float*)&a;
            const float* bv = (const float*)&b;
#pragma unroll
            for (int i = 0; i < 4; ++i)
#pragma unroll
                for (int j = 0; j < 4; ++j)
                    sa[i][j] = fmaf(av[i], bv[j], sa[i][j]);
        }

#pragma unroll
        for (int i = 0; i < 4; ++i) {
            int srow = qs + ty * 4 + i;
#pragma unroll
            for (int j = 0; j < 4; ++j) {
                float v = sa[i][j] * scale;
                if (ks + tx * 4 + j > srow) v = -1e30f;
                sa[i][j] = v;
            }
        }

#pragma unroll
        for (int i = 0; i < 4; ++i) {
            float rm = fmaxf(fmaxf(sa[i][0], sa[i][1]), fmaxf(sa[i][2], sa[i][3]));
#pragma unroll
            for (int off = 8; off; off >>= 1)
                rm = fmaxf(rm, __shfl_xor_sync(0xffffffffu, rm, off));
            float mnew = fmaxf(m[i], rm);
            float corr = __expf(m[i] - mnew);
            float rs = 0.0f;
#pragma unroll
            for (int j = 0; j < 4; ++j) {
                float p = __expf(sa[i][j] - mnew);
                sa[i][j] = p;
                rs += p;
            }
#pragma unroll
            for (int off = 8; off; off >>= 1)
                rs += __shfl_xor_sync(0xffffffffu, rs, off);
            l[i] = l[i] * corr + rs;
            m[i] = mnew;
#pragma unroll
            for (int j = 0; j < 8; ++j) o[i][j] *= corr;
            *(float4*)&Ps[(ty * 4 + i) * 64 + tx * 4] =
                make_float4(sa[i][0], sa[i][1], sa[i][2], sa[i][3]);
        }
        __syncthreads();

#pragma unroll 4
        for (int t = 0; t < 64; ++t) {
            float a0 = Ps[(ty * 4 + 0) * 64 + t];
            float a1 = Ps[(ty * 4 + 1) * 64 + t];
            float a2 = Ps[(ty * 4 + 2) * 64 + t];
            float a3 = Ps[(ty * 4 + 3) * 64 + t];
            float4 b0 = *(const float4*)&Vs[t * 128 + tx * 4];
            float4 b1 = *(const float4*)&Vs[t * 128 + 64 + tx * 4];
            const float* b0v = (const float*)&b0;
            const float* b1v = (const float*)&b1;
            float ar[4] = {a0, a1, a2, a3};
#pragma unroll
            for (int i = 0; i < 4; ++i) {
#pragma unroll
                for (int j = 0; j < 4; ++j) o[i][j]     = fmaf(ar[i], b0v[j], o[i][j]);
#pragma unroll
                for (int j = 0; j < 4; ++j) o[i][4 + j] = fmaf(ar[i], b1v[j], o[i][4 + j]);
            }
        }
        __syncthreads();
    }

#pragma unroll
    for (int i = 0; i < 4; ++i) {
        float inv = 1.0f / l[i];
        int s = qs + ty * 4 + i;
        float4 v0 = make_float4(o[i][0] * inv, o[i][1] * inv, o[i][2] * inv, o[i][3] * inv);
        float4 v1 = make_float4(o[i][4] * inv, o[i][5] * inv, o[i][6] * inv, o[i][7] * inv);
        *(float4*)&g_att[(size_t)s * D_MODEL + h * HDIM + tx * 4] = v0;
        *(float4*)&g_att[(size_t)s * D_MODEL + h * HDIM + 64 + tx * 4] = v1;
    }
}

// ---------------------------------------------------------------------------
extern "C" void kernel_launch(void* const* d_in, const int* in_sizes, int n_in,
                              void* d_out, int out_size)
{
    const float* x     = (const float*)d_in[0];
    const float* w_qkv = (const float*)d_in[1];
    const float* w_out = (const float*)d_in[2];
    const float* q_ln  = (const float*)d_in[3];
    const float* k_ln  = (const float*)d_in[4];
    float* out = (float*)d_out;

    void *qkv_p, *att_p;
    void *xh, *xl, *wqh, *wql, *woh, *wol, *ah, *al;
    cudaGetSymbolAddress(&qkv_p, g_qkv);
    cudaGetSymbolAddress(&att_p, g_att);
    cudaGetSymbolAddress(&xh, g_xh);   cudaGetSymbolAddress(&xl, g_xl);
    cudaGetSymbolAddress(&wqh, g_wqh); cudaGetSymbolAddress(&wql, g_wql);
    cudaGetSymbolAddress(&woh, g_woh); cudaGetSymbolAddress(&wol, g_wol);
    cudaGetSymbolAddress(&ah, g_ah);   cudaGetSymbolAddress(&al, g_al);

    cudaFuncSetAttribute(gemm_mma, cudaFuncAttributeMaxDynamicSharedMemorySize,
                         GSMEM);
    cudaFuncSetAttribute(attn_kernel, cudaFuncAttributeMaxDynamicSharedMemorySize,
                         (int)ATT_SMEM);

    // 0) split fp32 -> bf16 hi/lo
    {
        int n4 = (S_LEN * D_MODEL) / 4;
        split_kernel<<<(n4 + 255) / 256, 256>>>(x, (__nv_bfloat16*)xh,
                                                (__nv_bfloat16*)xl, n4);
        n4 = (QKV_N * D_MODEL) / 4;
        split_kernel<<<(n4 + 255) / 256, 256>>>(w_qkv, (__nv_bfloat16*)wqh,
                                                (__nv_bfloat16*)wql, n4);
        n4 = (D_MODEL * D_MODEL) / 4;
        split_kernel<<<(n4 + 255) / 256, 256>>>(w_out, (__nv_bfloat16*)woh,
                                                (__nv_bfloat16*)wol, n4);
    }

    // 1) QKV projection (mma.sync): [2048,6144]
    gemm_mma<<<dim3(QKV_N / BN, S_LEN / BM), 256, GSMEM>>>(
        (const __nv_bfloat16*)xh, (const __nv_bfloat16*)xl,
        (const __nv_bfloat16*)wqh, (const __nv_bfloat16*)wql,
        (float*)qkv_p, S_LEN, QKV_N, D_MODEL);

    // 2) RMSNorm + RoPE
    rmsrope_kernel<<<dim3(S_LEN, NH + NG), 128>>>(q_ln, k_ln);

    // 3) Flash attention -> g_att
    attn_kernel<<<dim3(S_LEN / 64, NH), 256, ATT_SMEM>>>();

    // 4) split attention output
    {
        int n4 = (S_LEN * D_MODEL) / 4;
        split_kernel<<<(n4 + 255) / 256, 256>>>((const float*)att_p,
                                                (__nv_bfloat16*)ah,
                                                (__nv_bfloat16*)al, n4);
    }

    // 5) Output projection (mma.sync): [2048,4096]
    gemm_mma<<<dim3(D_MODEL / BN, S_LEN / BM), 256, GSMEM>>>(
        (const __nv_bfloat16*)ah, (const __nv_bfloat16*)al,
        (const __nv_bfloat16*)woh, (const __nv_bfloat16*)wol,
        out, S_LEN, D_MODEL, D_MODEL);
}

// round 5
// speedup vs baseline: 2.9696x; 1.5122x over previous
#include <cuda_runtime.h>
#include <cuda_bf16.h>
#include <cstdint>
#include <math.h>

// Problem constants
#define S_LEN   2048
#define D_MODEL 4096
#define NH      32
#define NG      8
#define HDIM    128
#define QKV_N   6144          // D + 2*G*HD
#define V_OFF   5120          // D + G*HD
#define SCALE_ATT 0.08838834764831845f

// fp32 scratch
__device__ float g_qkv[(size_t)S_LEN * QKV_N];

// bf16 hi/lo split scratch
__device__ __nv_bfloat16 g_xh [(size_t)S_LEN * D_MODEL];
__device__ __nv_bfloat16 g_xl [(size_t)S_LEN * D_MODEL];
__device__ __nv_bfloat16 g_wqh[(size_t)QKV_N * D_MODEL];
__device__ __nv_bfloat16 g_wql[(size_t)QKV_N * D_MODEL];
__device__ __nv_bfloat16 g_woh[(size_t)D_MODEL * D_MODEL];
__device__ __nv_bfloat16 g_wol[(size_t)D_MODEL * D_MODEL];
__device__ __nv_bfloat16 g_ah [(size_t)S_LEN * D_MODEL];
__device__ __nv_bfloat16 g_al [(size_t)S_LEN * D_MODEL];
__device__ __nv_bfloat16 g_qh [(size_t)S_LEN * NH * HDIM];
__device__ __nv_bfloat16 g_ql [(size_t)S_LEN * NH * HDIM];
__device__ __nv_bfloat16 g_kh [(size_t)S_LEN * NG * HDIM];
__device__ __nv_bfloat16 g_kl [(size_t)S_LEN * NG * HDIM];
__device__ __nv_bfloat16 g_vh [(size_t)S_LEN * NG * HDIM];
__device__ __nv_bfloat16 g_vl [(size_t)S_LEN * NG * HDIM];

// ---------------------------------------------------------------------------
// helpers (portable sm_80+ PTX only — harness compiles for plain sm_100)
// ---------------------------------------------------------------------------
__device__ __forceinline__ uint32_t smem_u32(const void* p) {
    uint32_t a;
    asm("{ .reg .u64 t; cvta.to.shared.u64 t, %1; cvt.u32.u64 %0, t; }"
        : "=r"(a) : "l"(p));
    return a;
}
__device__ __forceinline__ uint32_t sw128(uint32_t x) {
    return x ^ ((x >> 3) & 0x70);
}
// 256B rows, 16B quads: conflict-free quad swizzle
__device__ __forceinline__ uint32_t swq(int row, int quad) {
    return (uint32_t)(row * 256 + (((quad & 8) | ((quad & 7) ^ (row & 7))) << 4));
}
__device__ __forceinline__ void cp16(uint32_t saddr, const void* gptr) {
    asm volatile("cp.async.cg.shared.global [%0], [%1], 16;"
                 :: "r"(saddr), "l"(gptr) : "memory");
}
__device__ __forceinline__ void ldmx4(uint32_t* r, uint32_t addr) {
    asm volatile("ldmatrix.sync.aligned.m8n8.x4.shared.b16 {%0,%1,%2,%3}, [%4];"
                 : "=r"(r[0]), "=r"(r[1]), "=r"(r[2]), "=r"(r[3]) : "r"(addr));
}
__device__ __forceinline__ void ldmx4t(uint32_t* r, uint32_t addr) {
    asm volatile("ldmatrix.sync.aligned.m8n8.x4.trans.shared.b16 {%0,%1,%2,%3}, [%4];"
                 : "=r"(r[0]), "=r"(r[1]), "=r"(r[2]), "=r"(r[3]) : "r"(addr));
}
__device__ __forceinline__ void ldmx2(uint32_t* r, uint32_t addr) {
    asm volatile("ldmatrix.sync.aligned.m8n8.x2.shared.b16 {%0,%1}, [%2];"
                 : "=r"(r[0]), "=r"(r[1]) : "r"(addr));
}
__device__ __forceinline__ void mma16816(float* c, const uint32_t* a,
                                         const uint32_t* b) {
    asm volatile(
        "mma.sync.aligned.m16n8k16.row.col.f32.bf16.bf16.f32 "
        "{%0,%1,%2,%3}, {%4,%5,%6,%7}, {%8,%9}, {%0,%1,%2,%3};"
        : "+f"(c[0]), "+f"(c[1]), "+f"(c[2]), "+f"(c[3])
        : "r"(a[0]), "r"(a[1]), "r"(a[2]), "r"(a[3]), "r"(b[0]), "r"(b[1]));
}
// split (a,b) -> packed bf16x2 hi (return) and lo (out param)
__device__ __forceinline__ uint32_t packsplit(float a, float b, uint32_t& lo) {
    __nv_bfloat16 ha = __float2bfloat16(a), hb = __float2bfloat16(b);
    __nv_bfloat16 la = __float2bfloat16(a - __bfloat162float(ha));
    __nv_bfloat16 lb = __float2bfloat16(b - __bfloat162float(hb));
    lo = (uint32_t)__bfloat16_as_ushort(la) | ((uint32_t)__bfloat16_as_ushort(lb) << 16);
    return (uint32_t)__bfloat16_as_ushort(ha) | ((uint32_t)__bfloat16_as_ushort(hb) << 16);
}

// ---------------------------------------------------------------------------
// fp32 -> bf16 hi/lo split (for x, w_qkv, w_out)
// ---------------------------------------------------------------------------
__global__ void split_kernel(const float* __restrict__ s,
                             __nv_bfloat16* __restrict__ h,
                             __nv_bfloat16* __restrict__ l, int n4)
{
    int i = blockIdx.x * blockDim.x + threadIdx.x;
    if (i >= n4) return;
    float4 v = ((const float4*)s)[i];
    __nv_bfloat16 h0 = __float2bfloat16(v.x);
    __nv_bfloat16 h1 = __float2bfloat16(v.y);
    __nv_bfloat16 h2 = __float2bfloat16(v.z);
    __nv_bfloat16 h3 = __float2bfloat16(v.w);
    __nv_bfloat16 l0 = __float2bfloat16(v.x - __bfloat162float(h0));
    __nv_bfloat16 l1 = __float2bfloat16(v.y - __bfloat162float(h1));
    __nv_bfloat16 l2 = __float2bfloat16(v.z - __bfloat162float(h2));
    __nv_bfloat16 l3 = __float2bfloat16(v.w - __bfloat162float(h3));
    ushort4 hv, lv;
    hv.x = __bfloat16_as_ushort(h0); hv.y = __bfloat16_as_ushort(h1);
    hv.z = __bfloat16_as_ushort(h2); hv.w = __bfloat16_as_ushort(h3);
    lv.x = __bfloat16_as_ushort(l0); lv.y = __bfloat16_as_ushort(l1);
    lv.z = __bfloat16_as_ushort(l2); lv.w = __bfloat16_as_ushort(l3);
    *(ushort4*)(h + 4 * (size_t)i) = hv;
    *(ushort4*)(l + 4 * (size_t)i) = lv;
}

// ---------------------------------------------------------------------------
// bf16 split GEMM via mma.sync (NT), 3-stage cp.async pipeline.
// ---------------------------------------------------------------------------
#define BM 128
#define BN 128
#define KC 64
#define STAGE_B  65536              // 4 tiles x 16KB
#define GSMEM    (3 * STAGE_B)      // 192 KB

__global__ __launch_bounds__(256, 1)
void gemm_mma(const __nv_bfloat16* __restrict__ Ah, const __nv_bfloat16* __restrict__ Al,
              const __nv_bfloat16* __restrict__ Bh, const __nv_bfloat16* __restrict__ Bl,
              float* __restrict__ C, int M, int N, int K)
{
    extern __shared__ __align__(1024) char smem[];
    const int tid  = threadIdx.x;
    const int wid  = tid >> 5;
    const int lane = tid & 31;
    const int bn   = blockIdx.x * BN;
    const int bm   = blockIdx.y * BM;
    const uint32_t sb = smem_u32(smem);

    const int mrow0 = (wid & 1) * 64;
    const int ncol0 = (wid >> 1) * 32;

    float acc[4][4][4];
#pragma unroll
    for (int mt = 0; mt < 4; ++mt)
#pragma unroll
        for (int nt = 0; nt < 4; ++nt)
#pragma unroll
            for (int r = 0; r < 4; ++r) acc[mt][nt][r] = 0.0f;

    const int nchunks = K / KC;   // 64 — always >= 3

    auto stage = [&](int c, int s) {
        const int k0 = c * KC;
        const uint32_t base = sb + (uint32_t)s * STAGE_B;
#pragma unroll
        for (int i = 0; i < 4; ++i) {
            int q   = tid + i * 256;
            int row = q >> 3;
            int col = q & 7;
            uint32_t soff = sw128((uint32_t)row * 128u + (uint32_t)col * 16u);
            size_t ga = (size_t)(bm + row) * K + k0 + col * 8;
            size_t gb = (size_t)(bn + row) * K + k0 + col * 8;
            cp16(base + soff,          Ah + ga);
            cp16(base + 16384 + soff,  Al + ga);
            cp16(base + 32768 + soff,  Bh + gb);
            cp16(base + 49152 + soff,  Bl + gb);
        }
        asm volatile("cp.async.commit_group;" ::: "memory");
    };

    stage(0, 0);
    stage(1, 1);
    stage(2, 2);

    for (int c = 0; c < nchunks; ++c) {
        const int buf = c % 3;
        if (c + 2 < nchunks)
            asm volatile("cp.async.wait_group 2;" ::: "memory");
        else if (c + 1 < nchunks)
            asm volatile("cp.async.wait_group 1;" ::: "memory");
        else
            asm volatile("cp.async.wait_group 0;" ::: "memory");
        __syncthreads();

        const uint32_t sAh = sb + (uint32_t)buf * STAGE_B;
        const uint32_t sAl = sAh + 16384;
        const uint32_t sBh = sAh + 32768;
        const uint32_t sBl = sAh + 49152;

#pragma unroll
        for (int kk = 0; kk < 4; ++kk) {
            uint32_t ah[4][4], al[4][4], bh[4][2], bl[4][2];
            const int arow = mrow0 + (lane & 15);
            const int acol = kk * 2 + (lane >> 4);
#pragma unroll
            for (int mt = 0; mt < 4; ++mt) {
                uint32_t off = sw128((uint32_t)(arow + mt * 16) * 128u +
                                     (uint32_t)acol * 16u);
                ldmx4(ah[mt], sAh + off);
                ldmx4(al[mt], sAl + off);
            }
            const int brow = ncol0 + (lane & 7);
            const int bcol = kk * 2 + ((lane >> 3) & 1);
#pragma unroll
            for (int nt = 0; nt < 4; ++nt) {
                uint32_t off = sw128((uint32_t)(brow + nt * 8) * 128u +
                                     (uint32_t)bcol * 16u);
                ldmx2(bh[nt], sBh + off);
                ldmx2(bl[nt], sBl + off);
            }
#pragma unroll
            for (int mt = 0; mt < 4; ++mt)
#pragma unroll
                for (int nt = 0; nt < 4; ++nt) {
                    mma16816(acc[mt][nt], ah[mt], bh[nt]);
                    mma16816(acc[mt][nt], ah[mt], bl[nt]);
                    mma16816(acc[mt][nt], al[mt], bh[nt]);
                }
        }
        __syncthreads();
        if (c + 3 < nchunks) stage(c + 3, (c + 3) % 3);
    }

#pragma unroll
    for (int mt = 0; mt < 4; ++mt) {
        int r0 = bm + mrow0 + mt * 16 + (lane >> 2);
#pragma unroll
        for (int nt = 0; nt < 4; ++nt) {
            int cc = bn + ncol0 + nt * 8 + (lane & 3) * 2;
            *(float2*)&C[(size_t)r0 * N + cc] =
                make_float2(acc[mt][nt][0], acc[mt][nt][1]);
            *(float2*)&C[(size_t)(r0 + 8) * N + cc] =
                make_float2(acc[mt][nt][2], acc[mt][nt][3]);
        }
    }
}

// ---------------------------------------------------------------------------
// RMSNorm + RoPE + bf16 hi/lo split. grid (S, 48):
// hh 0..31 = Q (norm+rope), 32..39 = K (norm+rope), 40..47 = V (split only).
// ---------------------------------------------------------------------------
__global__ void rmsrope_kernel(const float* __restrict__ qw,
                               const float* __restrict__ kw)
{
    const int s  = blockIdx.x;
    const int hh = blockIdx.y;
    const int d  = threadIdx.x;            // 0..127

    if (hh >= 40) {                        // V: split only
        int gv = hh - 40;
        float v = g_qkv[(size_t)s * QKV_N + V_OFF + gv * HDIM + d];
        __nv_bfloat16 hi = __float2bfloat16(v);
        __nv_bfloat16 lo = __float2bfloat16(v - __bfloat162float(hi));
        size_t o = ((size_t)s * NG + gv) * HDIM + d;
        g_vh[o] = hi; g_vl[o] = lo;
        return;
    }

    const bool isq = hh < NH;
    const float* src = isq ? (g_qkv + (size_t)s * QKV_N + hh * HDIM)
                           : (g_qkv + (size_t)s * QKV_N + D_MODEL + (hh - NH) * HDIM);
    float w = isq ? qw[d] : kw[d];
    float v = src[d];

    float ss = v * v;
#pragma unroll
    for (int off = 16; off; off >>= 1)
        ss += __shfl_xor_sync(0xffffffffu, ss, off);
    __shared__ float red[4];
    if ((d & 31) == 0) red[d >> 5] = ss;
    __syncthreads();
    float tot = red[0] + red[1] + red[2] + red[3];
    float rms = rsqrtf(tot * (1.0f / HDIM) + 1e-5f);
    float xn  = v * rms * w;

    int   i    = d >> 1;
    float freq = 1.0f / powf(1000000.0f, (float)(2 * i) * (1.0f / HDIM));
    float ang  = (float)s * freq;
    float c, sn;
    sincosf(ang, &sn, &c);
    float partner = __shfl_xor_sync(0xffffffffu, xn, 1);
    float out = (d & 1) ? (partner * sn + xn * c)
                        : (xn * c - partner * sn);

    __nv_bfloat16 hi = __float2bfloat16(out);
    __nv_bfloat16 lo = __float2bfloat16(out - __bfloat162float(hi));
    if (isq) {
        size_t o = ((size_t)s * NH + hh) * HDIM + d;
        g_qh[o] = hi; g_ql[o] = lo;
    } else {
        size_t o = ((size_t)s * NG + (hh - NH)) * HDIM + d;
        g_kh[o] = hi; g_kl[o] = lo;
    }
}

// ---------------------------------------------------------------------------
// Tensor-core flash attention (bf16 hi/lo split, causal, GQA).
// CTA: 128 q rows x one head; 8 warps, each owns 16 q rows.
// Per iter: 64 keys. K/V double-buffered cp.async.
// smem: Qh|Ql (64KB) + 2 stages x (Kh|Kl|Vh|Vl = 64KB) = 192KB.
// Q/K/V smem rows: 256B (128 cols bf16), quad-swizzled via swq().
// ---------------------------------------------------------------------------
#define ASMEM (192 * 1024)

__global__ __launch_bounds__(256, 1)
void attn_mma()
{
    extern __shared__ __align__(1024) char smem[];
    const uint32_t sb = smem_u32(smem);
    const int tid  = threadIdx.x;
    const int wid  = tid >> 5;
    const int lane = tid & 31;
    const int h    = blockIdx.x;
    const int g    = h >> 2;
    const int qt   = gridDim.y - 1 - blockIdx.y;   // heavy tiles first
    const int qs   = qt * 128;
    const int ktmax = 2 * qt + 1;

    const uint32_t sQh = sb, sQl = sb + 32768u;

    auto stage_kv = [&](int kt, int s) {
        const int ks = kt * 64;
        const uint32_t base = sb + 65536u + (uint32_t)s * 65536u;
#pragma unroll
        for (int i = 0; i < 4; ++i) {
            int q2  = tid + i * 256;          // 0..1023
            int row = q2 >> 4, quad = q2 & 15;
            uint32_t so = swq(row, quad);
            size_t gk = ((size_t)(ks + row) * NG + g) * HDIM + quad * 8;
            cp16(base + so,          g_kh + gk);
            cp16(base + 16384u + so, g_kl + gk);
            cp16(base + 32768u + so, g_vh + gk);
            cp16(base + 49152u + so, g_vl + gk);
        }
        asm volatile("cp.async.commit_group;" ::: "memory");
    };

    // prologue: Q + KV(0) in group 0, KV(1) in group 1
#pragma unroll
    for (int i = 0; i < 8; ++i) {
        int q2  = tid + i * 256;              // 0..2047
        int row = q2 >> 4, quad = q2 & 15;
        uint32_t so = swq(row, quad);
        size_t gq = ((size_t)(qs + row) * NH + h) * HDIM + quad * 8;
        cp16(sQh + so, g_qh + gq);
        cp16(sQl + so, g_ql + gq);
    }
    stage_kv(0, 0);
    stage_kv(1, 1);

    uint32_t qfh[8][4];
    float oacc[16][4];
    float m0 = -1e30f, m1 = -1e30f, l0 = 0.0f, l1 = 0.0f;
#pragma unroll
    for (int nt = 0; nt < 16; ++nt)
#pragma unroll
        for (int e = 0; e < 4; ++e) oacc[nt][e] = 0.0f;

    const int r  = lane >> 2;
    const int cb = (lane & 3) << 1;
    const int arow = wid * 16 + (lane & 15);
    const int ksel = lane >> 4;

    for (int kt = 0; kt <= ktmax; ++kt) {
        if (kt < ktmax)
            asm volatile("cp.async.wait_group 1;" ::: "memory");
        else
            asm volatile("cp.async.wait_group 0;" ::: "memory");
        __syncthreads();

        if (kt == 0) {   // cache Q-hi fragments (Q-lo reloaded per iter)
#pragma unroll
            for (int k8 = 0; k8 < 8; ++k8)
                ldmx4(qfh[k8], sQh + swq(arow, k8 * 2 + ksel));
        }

        const uint32_t kb = sb + 65536u + (uint32_t)(kt & 1) * 65536u;
        const int ks = kt * 64;

        // ---- S = Q K^T ----
        float sacc[8][4];
#pragma unroll
        for (int nt = 0; nt < 8; ++nt)
#pragma unroll
            for (int e = 0; e < 4; ++e) sacc[nt][e] = 0.0f;

#pragma unroll
        for (int k8 = 0; k8 < 8; ++k8) {
            uint32_t qfl[4];
            ldmx4(qfl, sQl + swq(arow, k8 * 2 + ksel));
            const int brow = (lane & 7) + ((lane & 16) >> 1);
            const int bq   = k8 * 2 + ((lane >> 3) & 1);
#pragma unroll
            for (int ntp = 0; ntp < 4; ++ntp) {
                uint32_t bh[4], bl[4];
                uint32_t off = swq(ntp * 16 + brow, bq);
                ldmx4(bh, kb + off);
                ldmx4(bl, kb + 16384u + off);
                mma16816(sacc[2 * ntp],     qfh[k8], bh);
                mma16816(sacc[2 * ntp],     qfh[k8], bl);
                mma16816(sacc[2 * ntp],     qfl,     bh);
                mma16816(sacc[2 * ntp + 1], qfh[k8], bh + 2);
                mma16816(sacc[2 * ntp + 1], qfh[k8], bl + 2);
                mma16816(sacc[2 * ntp + 1], qfl,     bh + 2);
            }
        }

        // ---- scale + mask ----
        const int R0 = qs + wid * 16 + r;
        const int R1 = R0 + 8;
#pragma unroll
        for (int nt = 0; nt < 8; ++nt)
#pragma unroll
            for (int e = 0; e < 4; ++e) sacc[nt][e] *= SCALE_ATT;
        if (kt >= 2 * qt) {
#pragma unroll
            for (int nt = 0; nt < 8; ++nt) {
                int c0 = ks + nt * 8 + cb;
                if (c0     > R0) sacc[nt][0] = -1e30f;
                if (c0 + 1 > R0) sacc[nt][1] = -1e30f;
                if (c0     > R1) sacc[nt][2] = -1e30f;
                if (c0 + 1 > R1) sacc[nt][3] = -1e30f;
            }
        }

        // ---- online softmax (rows R0, R1; 4-lane groups share a row) ----
        float rm0 = -1e30f, rm1 = -1e30f;
#pragma unroll
        for (int nt = 0; nt < 8; ++nt) {
            rm0 = fmaxf(rm0, fmaxf(sacc[nt][0], sacc[nt][1]));
            rm1 = fmaxf(rm1, fmaxf(sacc[nt][2], sacc[nt][3]));
        }
        rm0 = fmaxf(rm0, __shfl_xor_sync(0xffffffffu, rm0, 1));
        rm0 = fmaxf(rm0, __shfl_xor_sync(0xffffffffu, rm0, 2));
        rm1 = fmaxf(rm1, __shfl_xor_sync(0xffffffffu, rm1, 1));
        rm1 = fmaxf(rm1, __shfl_xor_sync(0xffffffffu, rm1, 2));
        float mn0 = fmaxf(m0, rm0), mn1 = fmaxf(m1, rm1);
        float corr0 = __expf(m0 - mn0), corr1 = __expf(m1 - mn1);
        float s0 = 0.0f, s1 = 0.0f;
#pragma unroll
        for (int nt = 0; nt < 8; ++nt) {
            sacc[nt][0] = __expf(sacc[nt][0] - mn0); s0 += sacc[nt][0];
            sacc[nt][1] = __expf(sacc[nt][1] - mn0); s0 += sacc[nt][1];
            sacc[nt][2] = __expf(sacc[nt][2] - mn1); s1 += sacc[nt][2];
            sacc[nt][3] = __expf(sacc[nt][3] - mn1); s1 += sacc[nt][3];
        }
        s0 += __shfl_xor_sync(0xffffffffu, s0, 1);
        s0 += __shfl_xor_sync(0xffffffffu, s0, 2);
        s1 += __shfl_xor_sync(0xffffffffu, s1, 1);
        s1 += __shfl_xor_sync(0xffffffffu, s1, 2);
        l0 = l0 * corr0 + s0; m0 = mn0;
        l1 = l1 * corr1 + s1; m1 = mn1;
#pragma unroll
        for (int nt = 0; nt < 16; ++nt) {
            oacc[nt][0] *= corr0; oacc[nt][1] *= corr0;
            oacc[nt][2] *= corr1; oacc[nt][3] *= corr1;
        }

        // ---- pack P -> bf16 hi/lo A-fragments (4 key-ksteps of 16) ----
        uint32_t ph[4][4], pl[4][4];
#pragma unroll
        for (int kv = 0; kv < 4; ++kv) {
            ph[kv][0] = packsplit(sacc[2 * kv][0],     sacc[2 * kv][1],     pl[kv][0]);
            ph[kv][1] = packsplit(sacc[2 * kv][2],     sacc[2 * kv][3],     pl[kv][1]);
            ph[kv][2] = packsplit(sacc[2 * kv + 1][0], sacc[2 * kv + 1][1], pl[kv][2]);
            ph[kv][3] = packsplit(sacc[2 * kv + 1][2], sacc[2 * kv + 1][3], pl[kv][3]);
        }

        // ---- O += P V  (V via ldmatrix.trans from [key][hd]) ----
        const uint32_t vb = kb + 32768u;
        const int vrow0 = (lane & 7) + (lane & 8);
        const int vqsel = lane >> 4;
#pragma unroll
        for (int kv = 0; kv < 4; ++kv) {
#pragma unroll
            for (int ntp = 0; ntp < 8; ++ntp) {
                uint32_t vh[4], vl[4];
                uint32_t off = swq(kv * 16 + vrow0, ntp * 2 + vqsel);
                ldmx4t(vh, vb + off);
                ldmx4t(vl, vb + 16384u + off);
                mma16816(oacc[2 * ntp],     ph[kv], vh);
                mma16816(oacc[2 * ntp],     ph[kv], vl);
                mma16816(oacc[2 * ntp],     pl[kv], vh);
                mma16816(oacc[2 * ntp + 1], ph[kv], vh + 2);
                mma16816(oacc[2 * ntp + 1], ph[kv], vl + 2);
                mma16816(oacc[2 * ntp + 1], pl[kv], vh + 2);
            }
        }
        __syncthreads();
        if (kt + 2 <= ktmax) stage_kv(kt + 2, kt & 1);
    }

    // ---- epilogue: normalize, split to bf16 hi/lo, write g_ah/g_al ----
    float inv0 = 1.0f / l0, inv1 = 1.0f / l1;
    int s0r = qs + wid * 16 + r, s1r = s0r + 8;
#pragma unroll
    for (int nt = 0; nt < 16; ++nt) {
        int col = h * HDIM + nt * 8 + cb;
        uint32_t lo0, lo1;
        uint32_t hi0 = packsplit(oacc[nt][0] * inv0, oacc[nt][1] * inv0, lo0);
        uint32_t hi1 = packsplit(oacc[nt][2] * inv1, oacc[nt][3] * inv1, lo1);
        *(uint32_t*)&g_ah[(size_t)s0r * D_MODEL + col] = hi0;
        *(uint32_t*)&g_al[(size_t)s0r * D_MODEL + col] = lo0;
        *(uint32_t*)&g_ah[(size_t)s1r * D_MODEL + col] = hi1;
        *(uint32_t*)&g_al[(size_t)s1r * D_MODEL + col] = lo1;
    }
}

// ---------------------------------------------------------------------------
extern "C" void kernel_launch(void* const* d_in, const int* in_sizes, int n_in,
                              void* d_out, int out_size)
{
    const float* x     = (const float*)d_in[0];
    const float* w_qkv = (const float*)d_in[1];
    const float* w_out = (const float*)d_in[2];
    const float* q_ln  = (const float*)d_in[3];
    const float* k_ln  = (const float*)d_in[4];
    float* out = (float*)d_out;

    void *qkv_p;
    void *xh, *xl, *wqh, *wql, *woh, *wol, *ah, *al;
    cudaGetSymbolAddress(&qkv_p, g_qkv);
    cudaGetSymbolAddress(&xh, g_xh);   cudaGetSymbolAddress(&xl, g_xl);
    cudaGetSymbolAddress(&wqh, g_wqh); cudaGetSymbolAddress(&wql, g_wql);
    cudaGetSymbolAddress(&woh, g_woh); cudaGetSymbolAddress(&wol, g_wol);
    cudaGetSymbolAddress(&ah, g_ah);   cudaGetSymbolAddress(&al, g_al);

    cudaFuncSetAttribute(gemm_mma, cudaFuncAttributeMaxDynamicSharedMemorySize,
                         GSMEM);
    cudaFuncSetAttribute(attn_mma, cudaFuncAttributeMaxDynamicSharedMemorySize,
                         ASMEM);

    // 0) split fp32 -> bf16 hi/lo
    {
        int n4 = (S_LEN * D_MODEL) / 4;
        split_kernel<<<(n4 + 255) / 256, 256>>>(x, (__nv_bfloat16*)xh,
                                                (__nv_bfloat16*)xl, n4);
        n4 = (QKV_N * D_MODEL) / 4;
        split_kernel<<<(n4 + 255) / 256, 256>>>(w_qkv, (__nv_bfloat16*)wqh,
                                                (__nv_bfloat16*)wql, n4);
        n4 = (D_MODEL * D_MODEL) / 4;
        split_kernel<<<(n4 + 255) / 256, 256>>>(w_out, (__nv_bfloat16*)woh,
                                                (__nv_bfloat16*)wol, n4);
    }

    // 1) QKV projection
    gemm_mma<<<dim3(QKV_N / BN, S_LEN / BM), 256, GSMEM>>>(
        (const __nv_bfloat16*)xh, (const __nv_bfloat16*)xl,
        (const __nv_bfloat16*)wqh, (const __nv_bfloat16*)wql,
        (float*)qkv_p, S_LEN, QKV_N, D_MODEL);

    // 2) RMSNorm + RoPE + splits (Q, K, V)
    rmsrope_kernel<<<dim3(S_LEN, NH + 2 * NG), 128>>>(q_ln, k_ln);

    // 3) Tensor-core flash attention -> g_ah/g_al
    attn_mma<<<dim3(NH, S_LEN / 128), 256, ASMEM>>>();

    // 4) Output projection
    gemm_mma<<<dim3(D_MODEL / BN, S_LEN / BM), 256, GSMEM>>>(
        (const __nv_bfloat16*)ah, (const __nv_bfloat16*)al,
        (const __nv_bfloat16*)woh, (const __nv_bfloat16*)wol,
        out, S_LEN, D_MODEL, D_MODEL);
}

// round 6
// speedup vs baseline: 3.3406x; 1.1249x over previous
#include <cuda_runtime.h>
#include <cuda_bf16.h>
#include <cuda_fp16.h>
#include <cstdint>
#include <math.h>

// Problem constants
#define S_LEN   2048
#define D_MODEL 4096
#define NH      32
#define NG      8
#define HDIM    128
#define QKV_N   6144          // D + 2*G*HD
#define V_OFF   5120          // D + G*HD
#define SCALE_ATT 0.08838834764831845f

// fp32 scratch
__device__ float g_qkv[(size_t)S_LEN * QKV_N];

// bf16 hi/lo split scratch (QKV path)
__device__ __nv_bfloat16 g_xh [(size_t)S_LEN * D_MODEL];
__device__ __nv_bfloat16 g_xl [(size_t)S_LEN * D_MODEL];
__device__ __nv_bfloat16 g_wqh[(size_t)QKV_N * D_MODEL];
__device__ __nv_bfloat16 g_wql[(size_t)QKV_N * D_MODEL];
__device__ __nv_bfloat16 g_qh [(size_t)S_LEN * NH * HDIM];
__device__ __nv_bfloat16 g_ql [(size_t)S_LEN * NH * HDIM];
__device__ __nv_bfloat16 g_kh [(size_t)S_LEN * NG * HDIM];
__device__ __nv_bfloat16 g_kl [(size_t)S_LEN * NG * HDIM];
__device__ __nv_bfloat16 g_vh [(size_t)S_LEN * NG * HDIM];
__device__ __nv_bfloat16 g_vl [(size_t)S_LEN * NG * HDIM];

// fp16 scratch (out-projection path: A = att hi/lo split, B = w_out rounded)
__device__ __half g_woh[(size_t)D_MODEL * D_MODEL];
__device__ __half g_ah [(size_t)S_LEN * D_MODEL];
__device__ __half g_al [(size_t)S_LEN * D_MODEL];

// ---------------------------------------------------------------------------
// helpers (portable sm_80+ PTX only — harness compiles for plain sm_100)
// ---------------------------------------------------------------------------
__device__ __forceinline__ uint32_t smem_u32(const void* p) {
    uint32_t a;
    asm("{ .reg .u64 t; cvta.to.shared.u64 t, %1; cvt.u32.u64 %0, t; }"
        : "=r"(a) : "l"(p));
    return a;
}
__device__ __forceinline__ uint32_t sw128(uint32_t x) {
    return x ^ ((x >> 3) & 0x70);
}
// 256B rows, 16B quads: conflict-free quad swizzle
__device__ __forceinline__ uint32_t swq(int row, int quad) {
    return (uint32_t)(row * 256 + (((quad & 8) | ((quad & 7) ^ (row & 7))) << 4));
}
__device__ __forceinline__ void cp16(uint32_t saddr, const void* gptr) {
    asm volatile("cp.async.cg.shared.global [%0], [%1], 16;"
                 :: "r"(saddr), "l"(gptr) : "memory");
}
__device__ __forceinline__ void ldmx4(uint32_t* r, uint32_t addr) {
    asm volatile("ldmatrix.sync.aligned.m8n8.x4.shared.b16 {%0,%1,%2,%3}, [%4];"
                 : "=r"(r[0]), "=r"(r[1]), "=r"(r[2]), "=r"(r[3]) : "r"(addr));
}
__device__ __forceinline__ void ldmx4t(uint32_t* r, uint32_t addr) {
    asm volatile("ldmatrix.sync.aligned.m8n8.x4.trans.shared.b16 {%0,%1,%2,%3}, [%4];"
                 : "=r"(r[0]), "=r"(r[1]), "=r"(r[2]), "=r"(r[3]) : "r"(addr));
}
__device__ __forceinline__ void ldmx2(uint32_t* r, uint32_t addr) {
    asm volatile("ldmatrix.sync.aligned.m8n8.x2.shared.b16 {%0,%1}, [%2];"
                 : "=r"(r[0]), "=r"(r[1]) : "r"(addr));
}
__device__ __forceinline__ void mma16816(float* c, const uint32_t* a,
                                         const uint32_t* b) {
    asm volatile(
        "mma.sync.aligned.m16n8k16.row.col.f32.bf16.bf16.f32 "
        "{%0,%1,%2,%3}, {%4,%5,%6,%7}, {%8,%9}, {%0,%1,%2,%3};"
        : "+f"(c[0]), "+f"(c[1]), "+f"(c[2]), "+f"(c[3])
        : "r"(a[0]), "r"(a[1]), "r"(a[2]), "r"(a[3]), "r"(b[0]), "r"(b[1]));
}
__device__ __forceinline__ void hmma16816(float* c, const uint32_t* a,
                                          const uint32_t* b) {
    asm volatile(
        "mma.sync.aligned.m16n8k16.row.col.f32.f16.f16.f32 "
        "{%0,%1,%2,%3}, {%4,%5,%6,%7}, {%8,%9}, {%0,%1,%2,%3};"
        : "+f"(c[0]), "+f"(c[1]), "+f"(c[2]), "+f"(c[3])
        : "r"(a[0]), "r"(a[1]), "r"(a[2]), "r"(a[3]), "r"(b[0]), "r"(b[1]));
}
// bf16 split (a,b) -> packed hi (return) and lo (out param)
__device__ __forceinline__ uint32_t packsplit(float a, float b, uint32_t& lo) {
    __nv_bfloat16 ha = __float2bfloat16(a), hb = __float2bfloat16(b);
    __nv_bfloat16 la = __float2bfloat16(a - __bfloat162float(ha));
    __nv_bfloat16 lb = __float2bfloat16(b - __bfloat162float(hb));
    lo = (uint32_t)__bfloat16_as_ushort(la) | ((uint32_t)__bfloat16_as_ushort(lb) << 16);
    return (uint32_t)__bfloat16_as_ushort(ha) | ((uint32_t)__bfloat16_as_ushort(hb) << 16);
}
// fp16 split (a,b) -> packed hi (return) and lo (out param)
__device__ __forceinline__ uint32_t packsplit_h(float a, float b, uint32_t& lo) {
    __half ha = __float2half_rn(a), hb = __float2half_rn(b);
    __half la = __float2half_rn(a - __half2float(ha));
    __half lb = __float2half_rn(b - __half2float(hb));
    lo = (uint32_t)__half_as_ushort(la) | ((uint32_t)__half_as_ushort(lb) << 16);
    return (uint32_t)__half_as_ushort(ha) | ((uint32_t)__half_as_ushort(hb) << 16);
}

// ---------------------------------------------------------------------------
// fp32 -> bf16 hi/lo split (x, w_qkv)
// ---------------------------------------------------------------------------
__global__ void split_kernel(const float* __restrict__ s,
                             __nv_bfloat16* __restrict__ h,
                             __nv_bfloat16* __restrict__ l, int n4)
{
    int i = blockIdx.x * blockDim.x + threadIdx.x;
    if (i >= n4) return;
    float4 v = ((const float4*)s)[i];
    __nv_bfloat16 h0 = __float2bfloat16(v.x);
    __nv_bfloat16 h1 = __float2bfloat16(v.y);
    __nv_bfloat16 h2 = __float2bfloat16(v.z);
    __nv_bfloat16 h3 = __float2bfloat16(v.w);
    __nv_bfloat16 l0 = __float2bfloat16(v.x - __bfloat162float(h0));
    __nv_bfloat16 l1 = __float2bfloat16(v.y - __bfloat162float(h1));
    __nv_bfloat16 l2 = __float2bfloat16(v.z - __bfloat162float(h2));
    __nv_bfloat16 l3 = __float2bfloat16(v.w - __bfloat162float(h3));
    ushort4 hv, lv;
    hv.x = __bfloat16_as_ushort(h0); hv.y = __bfloat16_as_ushort(h1);
    hv.z = __bfloat16_as_ushort(h2); hv.w = __bfloat16_as_ushort(h3);
    lv.x = __bfloat16_as_ushort(l0); lv.y = __bfloat16_as_ushort(l1);
    lv.z = __bfloat16_as_ushort(l2); lv.w = __bfloat16_as_ushort(l3);
    *(ushort4*)(h + 4 * (size_t)i) = hv;
    *(ushort4*)(l + 4 * (size_t)i) = lv;
}

// fp32 -> fp16 round only (w_out)
__global__ void round_h_kernel(const float* __restrict__ s,
                               __half* __restrict__ h, int n4)
{
    int i = blockIdx.x * blockDim.x + threadIdx.x;
    if (i >= n4) return;
    float4 v = ((const float4*)s)[i];
    ushort4 hv;
    hv.x = __half_as_ushort(__float2half_rn(v.x));
    hv.y = __half_as_ushort(__float2half_rn(v.y));
    hv.z = __half_as_ushort(__float2half_rn(v.z));
    hv.w = __half_as_ushort(__float2half_rn(v.w));
    *(ushort4*)(h + 4 * (size_t)i) = hv;
}

// ---------------------------------------------------------------------------
// bf16 3-term split GEMM (NT), single-barrier 3-stage cp.async pipeline.
// ---------------------------------------------------------------------------
#define BM 128
#define BN 128
#define KC 64
#define STAGE_B  65536              // 4 tiles x 16KB
#define GSMEM    (3 * STAGE_B)      // 192 KB

__global__ __launch_bounds__(256, 1)
void gemm_mma(const __nv_bfloat16* __restrict__ Ah, const __nv_bfloat16* __restrict__ Al,
              const __nv_bfloat16* __restrict__ Bh, const __nv_bfloat16* __restrict__ Bl,
              float* __restrict__ C, int M, int N, int K)
{
    extern __shared__ __align__(1024) char smem[];
    const int tid  = threadIdx.x;
    const int wid  = tid >> 5;
    const int lane = tid & 31;
    const int bn   = blockIdx.x * BN;
    const int bm   = blockIdx.y * BM;
    const uint32_t sb = smem_u32(smem);

    const int mrow0 = (wid & 1) * 64;
    const int ncol0 = (wid >> 1) * 32;

    float acc[4][4][4];
#pragma unroll
    for (int mt = 0; mt < 4; ++mt)
#pragma unroll
        for (int nt = 0; nt < 4; ++nt)
#pragma unroll
            for (int r = 0; r < 4; ++r) acc[mt][nt][r] = 0.0f;

    const int nchunks = K / KC;   // 64

    auto stage = [&](int c, int s) {
        const int k0 = c * KC;
        const uint32_t base = sb + (uint32_t)s * STAGE_B;
#pragma unroll
        for (int i = 0; i < 4; ++i) {
            int q   = tid + i * 256;
            int row = q >> 3;
            int col = q & 7;
            uint32_t soff = sw128((uint32_t)row * 128u + (uint32_t)col * 16u);
            size_t ga = (size_t)(bm + row) * K + k0 + col * 8;
            size_t gb = (size_t)(bn + row) * K + k0 + col * 8;
            cp16(base + soff,          Ah + ga);
            cp16(base + 16384 + soff,  Al + ga);
            cp16(base + 32768 + soff,  Bh + gb);
            cp16(base + 49152 + soff,  Bl + gb);
        }
        asm volatile("cp.async.commit_group;" ::: "memory");
    };

    stage(0, 0);
    stage(1, 1);

    for (int c = 0; c < nchunks; ++c) {
        if (c + 1 < nchunks)
            asm volatile("cp.async.wait_group 1;" ::: "memory");
        else
            asm volatile("cp.async.wait_group 0;" ::: "memory");
        __syncthreads();
        // prefetch into buf (c+2)%3 — last computed at iter c-1, freed by the sync
        if (c + 2 < nchunks) stage(c + 2, (c + 2) % 3);

        const int buf = c % 3;
        const uint32_t sAh = sb + (uint32_t)buf * STAGE_B;
        const uint32_t sAl = sAh + 16384;
        const uint32_t sBh = sAh + 32768;
        const uint32_t sBl = sAh + 49152;

#pragma unroll
        for (int kk = 0; kk < 4; ++kk) {
            uint32_t ah[4][4], al[4][4], bh[4][2], bl[4][2];
            const int arow = mrow0 + (lane & 15);
            const int acol = kk * 2 + (lane >> 4);
#pragma unroll
            for (int mt = 0; mt < 4; ++mt) {
                uint32_t off = sw128((uint32_t)(arow + mt * 16) * 128u +
                                     (uint32_t)acol * 16u);
                ldmx4(ah[mt], sAh + off);
                ldmx4(al[mt], sAl + off);
            }
            const int brow = ncol0 + (lane & 7);
            const int bcol = kk * 2 + ((lane >> 3) & 1);
#pragma unroll
            for (int nt = 0; nt < 4; ++nt) {
                uint32_t off = sw128((uint32_t)(brow + nt * 8) * 128u +
                                     (uint32_t)bcol * 16u);
                ldmx2(bh[nt], sBh + off);
                ldmx2(bl[nt], sBl + off);
            }
#pragma unroll
            for (int mt = 0; mt < 4; ++mt)
#pragma unroll
                for (int nt = 0; nt < 4; ++nt) {
                    mma16816(acc[mt][nt], ah[mt], bh[nt]);
                    mma16816(acc[mt][nt], ah[mt], bl[nt]);
                    mma16816(acc[mt][nt], al[mt], bh[nt]);
                }
        }
    }

#pragma unroll
    for (int mt = 0; mt < 4; ++mt) {
        int r0 = bm + mrow0 + mt * 16 + (lane >> 2);
#pragma unroll
        for (int nt = 0; nt < 4; ++nt) {
            int cc = bn + ncol0 + nt * 8 + (lane & 3) * 2;
            *(float2*)&C[(size_t)r0 * N + cc] =
                make_float2(acc[mt][nt][0], acc[mt][nt][1]);
            *(float2*)&C[(size_t)(r0 + 8) * N + cc] =
                make_float2(acc[mt][nt][2], acc[mt][nt][3]);
        }
    }
}

// ---------------------------------------------------------------------------
// fp16 2-term split GEMM (NT): C = (Ah+Al) * Bh^T, single-barrier pipeline.
// Stage = Ah|Al|Bh (48KB), 3 stages = 144KB.
// ---------------------------------------------------------------------------
#define STAGE2_B 49152
#define GSMEM2   (3 * STAGE2_B)     // 144 KB

__global__ __launch_bounds__(256, 1)
void gemm2_mma(const __half* __restrict__ Ah, const __half* __restrict__ Al,
               const __half* __restrict__ Bh,
               float* __restrict__ C, int M, int N, int K)
{
    extern __shared__ __align__(1024) char smem[];
    const int tid  = threadIdx.x;
    const int wid  = tid >> 5;
    const int lane = tid & 31;
    const int bn   = blockIdx.x * BN;
    const int bm   = blockIdx.y * BM;
    const uint32_t sb = smem_u32(smem);

    const int mrow0 = (wid & 1) * 64;
    const int ncol0 = (wid >> 1) * 32;

    float acc[4][4][4];
#pragma unroll
    for (int mt = 0; mt < 4; ++mt)
#pragma unroll
        for (int nt = 0; nt < 4; ++nt)
#pragma unroll
            for (int r = 0; r < 4; ++r) acc[mt][nt][r] = 0.0f;

    const int nchunks = K / KC;   // 64

    auto stage = [&](int c, int s) {
        const int k0 = c * KC;
        const uint32_t base = sb + (uint32_t)s * STAGE2_B;
#pragma unroll
        for (int i = 0; i < 4; ++i) {
            int q   = tid + i * 256;
            int row = q >> 3;
            int col = q & 7;
            uint32_t soff = sw128((uint32_t)row * 128u + (uint32_t)col * 16u);
            size_t ga = (size_t)(bm + row) * K + k0 + col * 8;
            size_t gb = (size_t)(bn + row) * K + k0 + col * 8;
            cp16(base + soff,          Ah + ga);
            cp16(base + 16384 + soff,  Al + ga);
            cp16(base + 32768 + soff,  Bh + gb);
        }
        asm volatile("cp.async.commit_group;" ::: "memory");
    };

    stage(0, 0);
    stage(1, 1);

    for (int c = 0; c < nchunks; ++c) {
        if (c + 1 < nchunks)
            asm volatile("cp.async.wait_group 1;" ::: "memory");
        else
            asm volatile("cp.async.wait_group 0;" ::: "memory");
        __syncthreads();
        if (c + 2 < nchunks) stage(c + 2, (c + 2) % 3);

        const int buf = c % 3;
        const uint32_t sAh = sb + (uint32_t)buf * STAGE2_B;
        const uint32_t sAl = sAh + 16384;
        const uint32_t sBh = sAh + 32768;

#pragma unroll
        for (int kk = 0; kk < 4; ++kk) {
            uint32_t ah[4][4], al[4][4], bh[4][2];
            const int arow = mrow0 + (lane & 15);
            const int acol = kk * 2 + (lane >> 4);
#pragma unroll
            for (int mt = 0; mt < 4; ++mt) {
                uint32_t off = sw128((uint32_t)(arow + mt * 16) * 128u +
                                     (uint32_t)acol * 16u);
                ldmx4(ah[mt], sAh + off);
                ldmx4(al[mt], sAl + off);
            }
            const int brow = ncol0 + (lane & 7);
            const int bcol = kk * 2 + ((lane >> 3) & 1);
#pragma unroll
            for (int nt = 0; nt < 4; ++nt) {
                uint32_t off = sw128((uint32_t)(brow + nt * 8) * 128u +
                                     (uint32_t)bcol * 16u);
                ldmx2(bh[nt], sBh + off);
            }
#pragma unroll
            for (int mt = 0; mt < 4; ++mt)
#pragma unroll
                for (int nt = 0; nt < 4; ++nt) {
                    hmma16816(acc[mt][nt], ah[mt], bh[nt]);
                    hmma16816(acc[mt][nt], al[mt], bh[nt]);
                }
        }
    }

#pragma unroll
    for (int mt = 0; mt < 4; ++mt) {
        int r0 = bm + mrow0 + mt * 16 + (lane >> 2);
#pragma unroll
        for (int nt = 0; nt < 4; ++nt) {
            int cc = bn + ncol0 + nt * 8 + (lane & 3) * 2;
            *(float2*)&C[(size_t)r0 * N + cc] =
                make_float2(acc[mt][nt][0], acc[mt][nt][1]);
            *(float2*)&C[(size_t)(r0 + 8) * N + cc] =
                make_float2(acc[mt][nt][2], acc[mt][nt][3]);
        }
    }
}

// ---------------------------------------------------------------------------
// RMSNorm + RoPE + bf16 hi/lo split. grid (S, 48):
// hh 0..31 = Q (norm+rope), 32..39 = K (norm+rope), 40..47 = V (split only).
// ---------------------------------------------------------------------------
__global__ void rmsrope_kernel(const float* __restrict__ qw,
                               const float* __restrict__ kw)
{
    const int s  = blockIdx.x;
    const int hh = blockIdx.y;
    const int d  = threadIdx.x;            // 0..127

    if (hh >= 40) {                        // V: split only
        int gv = hh - 40;
        float v = g_qkv[(size_t)s * QKV_N + V_OFF + gv * HDIM + d];
        __nv_bfloat16 hi = __float2bfloat16(v);
        __nv_bfloat16 lo = __float2bfloat16(v - __bfloat162float(hi));
        size_t o = ((size_t)s * NG + gv) * HDIM + d;
        g_vh[o] = hi; g_vl[o] = lo;
        return;
    }

    const bool isq = hh < NH;
    const float* src = isq ? (g_qkv + (size_t)s * QKV_N + hh * HDIM)
                           : (g_qkv + (size_t)s * QKV_N + D_MODEL + (hh - NH) * HDIM);
    float w = isq ? qw[d] : kw[d];
    float v = src[d];

    float ss = v * v;
#pragma unroll
    for (int off = 16; off; off >>= 1)
        ss += __shfl_xor_sync(0xffffffffu, ss, off);
    __shared__ float red[4];
    if ((d & 31) == 0) red[d >> 5] = ss;
    __syncthreads();
    float tot = red[0] + red[1] + red[2] + red[3];
    float rms = rsqrtf(tot * (1.0f / HDIM) + 1e-5f);
    float xn  = v * rms * w;

    int   i    = d >> 1;
    float freq = 1.0f / powf(1000000.0f, (float)(2 * i) * (1.0f / HDIM));
    float ang  = (float)s * freq;
    float c, sn;
    sincosf(ang, &sn, &c);
    float partner = __shfl_xor_sync(0xffffffffu, xn, 1);
    float out = (d & 1) ? (partner * sn + xn * c)
                        : (xn * c - partner * sn);

    __nv_bfloat16 hi = __float2bfloat16(out);
    __nv_bfloat16 lo = __float2bfloat16(out - __bfloat162float(hi));
    if (isq) {
        size_t o = ((size_t)s * NH + hh) * HDIM + d;
        g_qh[o] = hi; g_ql[o] = lo;
    } else {
        size_t o = ((size_t)s * NG + (hh - NH)) * HDIM + d;
        g_kh[o] = hi; g_kl[o] = lo;
    }
}

// ---------------------------------------------------------------------------
// Tensor-core flash attention (bf16 hi/lo split, causal, GQA).
// CTA: 128 q rows x one head; 8 warps, each owns 16 q rows.
// Per iter: 64 keys. K/V double-buffered cp.async. smem 192KB.
// ---------------------------------------------------------------------------
#define ASMEM (192 * 1024)

__global__ __launch_bounds__(256, 1)
void attn_mma()
{
    extern __shared__ __align__(1024) char smem[];
    const uint32_t sb = smem_u32(smem);
    const int tid  = threadIdx.x;
    const int wid  = tid >> 5;
    const int lane = tid & 31;
    const int h    = blockIdx.x;
    const int g    = h >> 2;
    const int qt   = gridDim.y - 1 - blockIdx.y;   // heavy tiles first
    const int qs   = qt * 128;
    const int ktmax = 2 * qt + 1;

    const uint32_t sQh = sb, sQl = sb + 32768u;

    auto stage_kv = [&](int kt, int s) {
        const int ks = kt * 64;
        const uint32_t base = sb + 65536u + (uint32_t)s * 65536u;
#pragma unroll
        for (int i = 0; i < 4; ++i) {
            int q2  = tid + i * 256;          // 0..1023
            int row = q2 >> 4, quad = q2 & 15;
            uint32_t so = swq(row, quad);
            size_t gk = ((size_t)(ks + row) * NG + g) * HDIM + quad * 8;
            cp16(base + so,          g_kh + gk);
            cp16(base + 16384u + so, g_kl + gk);
            cp16(base + 32768u + so, g_vh + gk);
            cp16(base + 49152u + so, g_vl + gk);
        }
        asm volatile("cp.async.commit_group;" ::: "memory");
    };

    // prologue: Q + KV(0) in group 0, KV(1) in group 1
#pragma unroll
    for (int i = 0; i < 8; ++i) {
        int q2  = tid + i * 256;              // 0..2047
        int row = q2 >> 4, quad = q2 & 15;
        uint32_t so = swq(row, quad);
        size_t gq = ((size_t)(qs + row) * NH + h) * HDIM + quad * 8;
        cp16(sQh + so, g_qh + gq);
        cp16(sQl + so, g_ql + gq);
    }
    stage_kv(0, 0);
    stage_kv(1, 1);

    uint32_t qfh[8][4];
    float oacc[16][4];
    float m0 = -1e30f, m1 = -1e30f, l0 = 0.0f, l1 = 0.0f;
#pragma unroll
    for (int nt = 0; nt < 16; ++nt)
#pragma unroll
        for (int e = 0; e < 4; ++e) oacc[nt][e] = 0.0f;

    const int r  = lane >> 2;
    const int cb = (lane & 3) << 1;
    const int arow = wid * 16 + (lane & 15);
    const int ksel = lane >> 4;

    for (int kt = 0; kt <= ktmax; ++kt) {
        if (kt < ktmax)
            asm volatile("cp.async.wait_group 1;" ::: "memory");
        else
            asm volatile("cp.async.wait_group 0;" ::: "memory");
        __syncthreads();

        if (kt == 0) {   // cache Q-hi fragments (Q-lo reloaded per iter)
#pragma unroll
            for (int k8 = 0; k8 < 8; ++k8)
                ldmx4(qfh[k8], sQh + swq(arow, k8 * 2 + ksel));
        }

        const uint32_t kb = sb + 65536u + (uint32_t)(kt & 1) * 65536u;
        const int ks = kt * 64;

        // ---- S = Q K^T ----
        float sacc[8][4];
#pragma unroll
        for (int nt = 0; nt < 8; ++nt)
#pragma unroll
            for (int e = 0; e < 4; ++e) sacc[nt][e] = 0.0f;

#pragma unroll
        for (int k8 = 0; k8 < 8; ++k8) {
            uint32_t qfl[4];
            ldmx4(qfl, sQl + swq(arow, k8 * 2 + ksel));
            const int brow = (lane & 7) + ((lane & 16) >> 1);
            const int bq   = k8 * 2 + ((lane >> 3) & 1);
#pragma unroll
            for (int ntp = 0; ntp < 4; ++ntp) {
                uint32_t bh[4], bl[4];
                uint32_t off = swq(ntp * 16 + brow, bq);
                ldmx4(bh, kb + off);
                ldmx4(bl, kb + 16384u + off);
                mma16816(sacc[2 * ntp],     qfh[k8], bh);
                mma16816(sacc[2 * ntp],     qfh[k8], bl);
                mma16816(sacc[2 * ntp],     qfl,     bh);
                mma16816(sacc[2 * ntp + 1], qfh[k8], bh + 2);
                mma16816(sacc[2 * ntp + 1], qfh[k8], bl + 2);
                mma16816(sacc[2 * ntp + 1], qfl,     bh + 2);
            }
        }

        // ---- scale + mask ----
        const int R0 = qs + wid * 16 + r;
        const int R1 = R0 + 8;
#pragma unroll
        for (int nt = 0; nt < 8; ++nt)
#pragma unroll
            for (int e = 0; e < 4; ++e) sacc[nt][e] *= SCALE_ATT;
        if (kt >= 2 * qt) {
#pragma unroll
            for (int nt = 0; nt < 8; ++nt) {
                int c0 = ks + nt * 8 + cb;
                if (c0     > R0) sacc[nt][0] = -1e30f;
                if (c0 + 1 > R0) sacc[nt][1] = -1e30f;
                if (c0     > R1) sacc[nt][2] = -1e30f;
                if (c0 + 1 > R1) sacc[nt][3] = -1e30f;
            }
        }

        // ---- online softmax ----
        float rm0 = -1e30f, rm1 = -1e30f;
#pragma unroll
        for (int nt = 0; nt < 8; ++nt) {
            rm0 = fmaxf(rm0, fmaxf(sacc[nt][0], sacc[nt][1]));
            rm1 = fmaxf(rm1, fmaxf(sacc[nt][2], sacc[nt][3]));
        }
        rm0 = fmaxf(rm0, __shfl_xor_sync(0xffffffffu, rm0, 1));
        rm0 = fmaxf(rm0, __shfl_xor_sync(0xffffffffu, rm0, 2));
        rm1 = fmaxf(rm1, __shfl_xor_sync(0xffffffffu, rm1, 1));
        rm1 = fmaxf(rm1, __shfl_xor_sync(0xffffffffu, rm1, 2));
        float mn0 = fmaxf(m0, rm0), mn1 = fmaxf(m1, rm1);
        float corr0 = __expf(m0 - mn0), corr1 = __expf(m1 - mn1);
        float s0 = 0.0f, s1 = 0.0f;
#pragma unroll
        for (int nt = 0; nt < 8; ++nt) {
            sacc[nt][0] = __expf(sacc[nt][0] - mn0); s0 += sacc[nt][0];
            sacc[nt][1] = __expf(sacc[nt][1] - mn0); s0 += sacc[nt][1];
            sacc[nt][2] = __expf(sacc[nt][2] - mn1); s1 += sacc[nt][2];
            sacc[nt][3] = __expf(sacc[nt][3] - mn1); s1 += sacc[nt][3];
        }
        s0 += __shfl_xor_sync(0xffffffffu, s0, 1);
        s0 += __shfl_xor_sync(0xffffffffu, s0, 2);
        s1 += __shfl_xor_sync(0xffffffffu, s1, 1);
        s1 += __shfl_xor_sync(0xffffffffu, s1, 2);
        l0 = l0 * corr0 + s0; m0 = mn0;
        l1 = l1 * corr1 + s1; m1 = mn1;
#pragma unroll
        for (int nt = 0; nt < 16; ++nt) {
            oacc[nt][0] *= corr0; oacc[nt][1] *= corr0;
            oacc[nt][2] *= corr1; oacc[nt][3] *= corr1;
        }

        // ---- pack P -> bf16 hi/lo A-fragments ----
        uint32_t ph[4][4], pl[4][4];
#pragma unroll
        for (int kv = 0; kv < 4; ++kv) {
            ph[kv][0] = packsplit(sacc[2 * kv][0],     sacc[2 * kv][1],     pl[kv][0]);
            ph[kv][1] = packsplit(sacc[2 * kv][2],     sacc[2 * kv][3],     pl[kv][1]);
            ph[kv][2] = packsplit(sacc[2 * kv + 1][0], sacc[2 * kv + 1][1], pl[kv][2]);
            ph[kv][3] = packsplit(sacc[2 * kv + 1][2], sacc[2 * kv + 1][3], pl[kv][3]);
        }

        // ---- O += P V ----
        const uint32_t vb = kb + 32768u;
        const int vrow0 = (lane & 7) + (lane & 8);
        const int vqsel = lane >> 4;
#pragma unroll
        for (int kv = 0; kv < 4; ++kv) {
#pragma unroll
            for (int ntp = 0; ntp < 8; ++ntp) {
                uint32_t vh[4], vl[4];
                uint32_t off = swq(kv * 16 + vrow0, ntp * 2 + vqsel);
                ldmx4t(vh, vb + off);
                ldmx4t(vl, vb + 16384u + off);
                mma16816(oacc[2 * ntp],     ph[kv], vh);
                mma16816(oacc[2 * ntp],     ph[kv], vl);
                mma16816(oacc[2 * ntp],     pl[kv], vh);
                mma16816(oacc[2 * ntp + 1], ph[kv], vh + 2);
                mma16816(oacc[2 * ntp + 1], ph[kv], vl + 2);
                mma16816(oacc[2 * ntp + 1], pl[kv], vh + 2);
            }
        }
        __syncthreads();
        if (kt + 2 <= ktmax) stage_kv(kt + 2, kt & 1);
    }

    // ---- epilogue: normalize, split to fp16 hi/lo for the out-projection ----
    float inv0 = 1.0f / l0, inv1 = 1.0f / l1;
    int s0r = qs + wid * 16 + r, s1r = s0r + 8;
#pragma unroll
    for (int nt = 0; nt < 16; ++nt) {
        int col = h * HDIM + nt * 8 + cb;
        uint32_t lo0, lo1;
        uint32_t hi0 = packsplit_h(oacc[nt][0] * inv0, oacc[nt][1] * inv0, lo0);
        uint32_t hi1 = packsplit_h(oacc[nt][2] * inv1, oacc[nt][3] * inv1, lo1);
        *(uint32_t*)&g_ah[(size_t)s0r * D_MODEL + col] = hi0;
        *(uint32_t*)&g_al[(size_t)s0r * D_MODEL + col] = lo0;
        *(uint32_t*)&g_ah[(size_t)s1r * D_MODEL + col] = hi1;
        *(uint32_t*)&g_al[(size_t)s1r * D_MODEL + col] = lo1;
    }
}

// ---------------------------------------------------------------------------
extern "C" void kernel_launch(void* const* d_in, const int* in_sizes, int n_in,
                              void* d_out, int out_size)
{
    const float* x     = (const float*)d_in[0];
    const float* w_qkv = (const float*)d_in[1];
    const float* w_out = (const float*)d_in[2];
    const float* q_ln  = (const float*)d_in[3];
    const float* k_ln  = (const float*)d_in[4];
    float* out = (float*)d_out;

    void *qkv_p;
    void *xh, *xl, *wqh, *wql, *woh, *ah, *al;
    cudaGetSymbolAddress(&qkv_p, g_qkv);
    cudaGetSymbolAddress(&xh, g_xh);   cudaGetSymbolAddress(&xl, g_xl);
    cudaGetSymbolAddress(&wqh, g_wqh); cudaGetSymbolAddress(&wql, g_wql);
    cudaGetSymbolAddress(&woh, g_woh);
    cudaGetSymbolAddress(&ah, g_ah);   cudaGetSymbolAddress(&al, g_al);

    cudaFuncSetAttribute(gemm_mma, cudaFuncAttributeMaxDynamicSharedMemorySize,
                         GSMEM);
    cudaFuncSetAttribute(gemm2_mma, cudaFuncAttributeMaxDynamicSharedMemorySize,
                         GSMEM2);
    cudaFuncSetAttribute(attn_mma, cudaFuncAttributeMaxDynamicSharedMemorySize,
                         ASMEM);

    // 0) splits: x, w_qkv -> bf16 hi/lo; w_out -> fp16 round
    {
        int n4 = (S_LEN * D_MODEL) / 4;
        split_kernel<<<(n4 + 255) / 256, 256>>>(x, (__nv_bfloat16*)xh,
                                                (__nv_bfloat16*)xl, n4);
        n4 = (QKV_N * D_MODEL) / 4;
        split_kernel<<<(n4 + 255) / 256, 256>>>(w_qkv, (__nv_bfloat16*)wqh,
                                                (__nv_bfloat16*)wql, n4);
        n4 = (D_MODEL * D_MODEL) / 4;
        round_h_kernel<<<(n4 + 255) / 256, 256>>>(w_out, (__half*)woh, n4);
    }

    // 1) QKV projection (bf16 3-term)
    gemm_mma<<<dim3(QKV_N / BN, S_LEN / BM), 256, GSMEM>>>(
        (const __nv_bfloat16*)xh, (const __nv_bfloat16*)xl,
        (const __nv_bfloat16*)wqh, (const __nv_bfloat16*)wql,
        (float*)qkv_p, S_LEN, QKV_N, D_MODEL);

    // 2) RMSNorm + RoPE + splits (Q, K, V)
    rmsrope_kernel<<<dim3(S_LEN, NH + 2 * NG), 128>>>(q_ln, k_ln);

    // 3) Tensor-core flash attention -> g_ah/g_al (fp16 hi/lo)
    attn_mma<<<dim3(NH, S_LEN / 128), 256, ASMEM>>>();

    // 4) Output projection (fp16 2-term)
    gemm2_mma<<<dim3(D_MODEL / BN, S_LEN / BM), 256, GSMEM2>>>(
        (const __half*)ah, (const __half*)al, (const __half*)woh,
        out, S_LEN, D_MODEL, D_MODEL);
}

// round 7
// speedup vs baseline: 3.9474x; 1.1817x over previous
#include <cuda_runtime.h>
#include <cuda_bf16.h>
#include <cuda_fp16.h>
#include <cstdint>
#include <math.h>

// Problem constants
#define S_LEN   2048
#define D_MODEL 4096
#define NH      32
#define NG      8
#define HDIM    128
#define QKV_N   6144          // D + 2*G*HD
#define V_OFF   5120          // D + G*HD
#define SCALE_ATT 0.08838834764831845f

// fp32 scratch
__device__ float g_qkv[(size_t)S_LEN * QKV_N];

// fp16 scratch (QKV projection: A = x hi/lo split, B = w_qkv rounded)
__device__ __half g_xh [(size_t)S_LEN * D_MODEL];
__device__ __half g_xl [(size_t)S_LEN * D_MODEL];
__device__ __half g_wqh[(size_t)QKV_N * D_MODEL];

// bf16 hi/lo split scratch (attention path)
__device__ __nv_bfloat16 g_qh [(size_t)S_LEN * NH * HDIM];
__device__ __nv_bfloat16 g_ql [(size_t)S_LEN * NH * HDIM];
__device__ __nv_bfloat16 g_kh [(size_t)S_LEN * NG * HDIM];
__device__ __nv_bfloat16 g_kl [(size_t)S_LEN * NG * HDIM];
__device__ __nv_bfloat16 g_vh [(size_t)S_LEN * NG * HDIM];
__device__ __nv_bfloat16 g_vl [(size_t)S_LEN * NG * HDIM];

// fp16 scratch (out-projection: A = att hi/lo split, B = w_out rounded)
__device__ __half g_woh[(size_t)D_MODEL * D_MODEL];
__device__ __half g_ah [(size_t)S_LEN * D_MODEL];
__device__ __half g_al [(size_t)S_LEN * D_MODEL];

// ---------------------------------------------------------------------------
// helpers (portable sm_80+ PTX only — harness compiles for plain sm_100)
// ---------------------------------------------------------------------------
__device__ __forceinline__ uint32_t smem_u32(const void* p) {
    uint32_t a;
    asm("{ .reg .u64 t; cvta.to.shared.u64 t, %1; cvt.u32.u64 %0, t; }"
        : "=r"(a) : "l"(p));
    return a;
}
__device__ __forceinline__ uint32_t sw128(uint32_t x) {
    return x ^ ((x >> 3) & 0x70);
}
// 256B rows, 16B quads: conflict-free quad swizzle
__device__ __forceinline__ uint32_t swq(int row, int quad) {
    return (uint32_t)(row * 256 + (((quad & 8) | ((quad & 7) ^ (row & 7))) << 4));
}
__device__ __forceinline__ void cp16(uint32_t saddr, const void* gptr) {
    asm volatile("cp.async.cg.shared.global [%0], [%1], 16;"
                 :: "r"(saddr), "l"(gptr) : "memory");
}
__device__ __forceinline__ void ldmx4(uint32_t* r, uint32_t addr) {
    asm volatile("ldmatrix.sync.aligned.m8n8.x4.shared.b16 {%0,%1,%2,%3}, [%4];"
                 : "=r"(r[0]), "=r"(r[1]), "=r"(r[2]), "=r"(r[3]) : "r"(addr));
}
__device__ __forceinline__ void ldmx4t(uint32_t* r, uint32_t addr) {
    asm volatile("ldmatrix.sync.aligned.m8n8.x4.trans.shared.b16 {%0,%1,%2,%3}, [%4];"
                 : "=r"(r[0]), "=r"(r[1]), "=r"(r[2]), "=r"(r[3]) : "r"(addr));
}
__device__ __forceinline__ void ldmx2(uint32_t* r, uint32_t addr) {
    asm volatile("ldmatrix.sync.aligned.m8n8.x2.shared.b16 {%0,%1}, [%2];"
                 : "=r"(r[0]), "=r"(r[1]) : "r"(addr));
}
__device__ __forceinline__ void mma16816(float* c, const uint32_t* a,
                                         const uint32_t* b) {
    asm volatile(
        "mma.sync.aligned.m16n8k16.row.col.f32.bf16.bf16.f32 "
        "{%0,%1,%2,%3}, {%4,%5,%6,%7}, {%8,%9}, {%0,%1,%2,%3};"
        : "+f"(c[0]), "+f"(c[1]), "+f"(c[2]), "+f"(c[3])
        : "r"(a[0]), "r"(a[1]), "r"(a[2]), "r"(a[3]), "r"(b[0]), "r"(b[1]));
}
__device__ __forceinline__ void hmma16816(float* c, const uint32_t* a,
                                          const uint32_t* b) {
    asm volatile(
        "mma.sync.aligned.m16n8k16.row.col.f32.f16.f16.f32 "
        "{%0,%1,%2,%3}, {%4,%5,%6,%7}, {%8,%9}, {%0,%1,%2,%3};"
        : "+f"(c[0]), "+f"(c[1]), "+f"(c[2]), "+f"(c[3])
        : "r"(a[0]), "r"(a[1]), "r"(a[2]), "r"(a[3]), "r"(b[0]), "r"(b[1]));
}
// bf16 split (a,b) -> packed hi (return) and lo (out param)
__device__ __forceinline__ uint32_t packsplit(float a, float b, uint32_t& lo) {
    __nv_bfloat16 ha = __float2bfloat16(a), hb = __float2bfloat16(b);
    __nv_bfloat16 la = __float2bfloat16(a - __bfloat162float(ha));
    __nv_bfloat16 lb = __float2bfloat16(b - __bfloat162float(hb));
    lo = (uint32_t)__bfloat16_as_ushort(la) | ((uint32_t)__bfloat16_as_ushort(lb) << 16);
    return (uint32_t)__bfloat16_as_ushort(ha) | ((uint32_t)__bfloat16_as_ushort(hb) << 16);
}
// fp16 split (a,b) -> packed hi (return) and lo (out param)
__device__ __forceinline__ uint32_t packsplit_h(float a, float b, uint32_t& lo) {
    __half ha = __float2half_rn(a), hb = __float2half_rn(b);
    __half la = __float2half_rn(a - __half2float(ha));
    __half lb = __float2half_rn(b - __half2float(hb));
    lo = (uint32_t)__half_as_ushort(la) | ((uint32_t)__half_as_ushort(lb) << 16);
    return (uint32_t)__half_as_ushort(ha) | ((uint32_t)__half_as_ushort(hb) << 16);
}

// ---------------------------------------------------------------------------
// fp32 -> fp16 hi/lo split (x)
// ---------------------------------------------------------------------------
__global__ void split_h_kernel(const float* __restrict__ s,
                               __half* __restrict__ h,
                               __half* __restrict__ l, int n4)
{
    int i = blockIdx.x * blockDim.x + threadIdx.x;
    if (i >= n4) return;
    float4 v = ((const float4*)s)[i];
    __half h0 = __float2half_rn(v.x);
    __half h1 = __float2half_rn(v.y);
    __half h2 = __float2half_rn(v.z);
    __half h3 = __float2half_rn(v.w);
    __half l0 = __float2half_rn(v.x - __half2float(h0));
    __half l1 = __float2half_rn(v.y - __half2float(h1));
    __half l2 = __float2half_rn(v.z - __half2float(h2));
    __half l3 = __float2half_rn(v.w - __half2float(h3));
    ushort4 hv, lv;
    hv.x = __half_as_ushort(h0); hv.y = __half_as_ushort(h1);
    hv.z = __half_as_ushort(h2); hv.w = __half_as_ushort(h3);
    lv.x = __half_as_ushort(l0); lv.y = __half_as_ushort(l1);
    lv.z = __half_as_ushort(l2); lv.w = __half_as_ushort(l3);
    *(ushort4*)(h + 4 * (size_t)i) = hv;
    *(ushort4*)(l + 4 * (size_t)i) = lv;
}

// fp32 -> fp16 round only (w_qkv, w_out)
__global__ void round_h_kernel(const float* __restrict__ s,
                               __half* __restrict__ h, int n4)
{
    int i = blockIdx.x * blockDim.x + threadIdx.x;
    if (i >= n4) return;
    float4 v = ((const float4*)s)[i];
    ushort4 hv;
    hv.x = __half_as_ushort(__float2half_rn(v.x));
    hv.y = __half_as_ushort(__float2half_rn(v.y));
    hv.z = __half_as_ushort(__float2half_rn(v.z));
    hv.w = __half_as_ushort(__float2half_rn(v.w));
    *(ushort4*)(h + 4 * (size_t)i) = hv;
}

// ---------------------------------------------------------------------------
// fp16 2-term split GEMM (NT): C = (Ah+Al) * Bh^T, single-barrier pipeline.
// CTA 128x128, 8 warps, warp tile 64x32, K-chunk 64.
// Stage = Ah|Al|Bh (48KB), 3 stages = 144KB.
// ---------------------------------------------------------------------------
#define BM 128
#define BN 128
#define KC 64
#define STAGE2_B 49152
#define GSMEM2   (3 * STAGE2_B)     // 144 KB

__global__ __launch_bounds__(256, 1)
void gemm2_mma(const __half* __restrict__ Ah, const __half* __restrict__ Al,
               const __half* __restrict__ Bh,
               float* __restrict__ C, int M, int N, int K)
{
    extern __shared__ __align__(1024) char smem[];
    const int tid  = threadIdx.x;
    const int wid  = tid >> 5;
    const int lane = tid & 31;
    const int bn   = blockIdx.x * BN;
    const int bm   = blockIdx.y * BM;
    const uint32_t sb = smem_u32(smem);

    const int mrow0 = (wid & 1) * 64;
    const int ncol0 = (wid >> 1) * 32;

    float acc[4][4][4];
#pragma unroll
    for (int mt = 0; mt < 4; ++mt)
#pragma unroll
        for (int nt = 0; nt < 4; ++nt)
#pragma unroll
            for (int r = 0; r < 4; ++r) acc[mt][nt][r] = 0.0f;

    const int nchunks = K / KC;   // 64

    auto stage = [&](int c, int s) {
        const int k0 = c * KC;
        const uint32_t base = sb + (uint32_t)s * STAGE2_B;
#pragma unroll
        for (int i = 0; i < 4; ++i) {
            int q   = tid + i * 256;
            int row = q >> 3;
            int col = q & 7;
            uint32_t soff = sw128((uint32_t)row * 128u + (uint32_t)col * 16u);
            size_t ga = (size_t)(bm + row) * K + k0 + col * 8;
            size_t gb = (size_t)(bn + row) * K + k0 + col * 8;
            cp16(base + soff,          Ah + ga);
            cp16(base + 16384 + soff,  Al + ga);
            cp16(base + 32768 + soff,  Bh + gb);
        }
        asm volatile("cp.async.commit_group;" ::: "memory");
    };

    stage(0, 0);
    stage(1, 1);

    for (int c = 0; c < nchunks; ++c) {
        if (c + 1 < nchunks)
            asm volatile("cp.async.wait_group 1;" ::: "memory");
        else
            asm volatile("cp.async.wait_group 0;" ::: "memory");
        __syncthreads();
        // prefetch into buf (c+2)%3 — last computed at iter c-1, freed by the sync
        if (c + 2 < nchunks) stage(c + 2, (c + 2) % 3);

        const int buf = c % 3;
        const uint32_t sAh = sb + (uint32_t)buf * STAGE2_B;
        const uint32_t sAl = sAh + 16384;
        const uint32_t sBh = sAh + 32768;

#pragma unroll
        for (int kk = 0; kk < 4; ++kk) {
            uint32_t ah[4][4], al[4][4], bh[4][2];
            const int arow = mrow0 + (lane & 15);
            const int acol = kk * 2 + (lane >> 4);
#pragma unroll
            for (int mt = 0; mt < 4; ++mt) {
                uint32_t off = sw128((uint32_t)(arow + mt * 16) * 128u +
                                     (uint32_t)acol * 16u);
                ldmx4(ah[mt], sAh + off);
                ldmx4(al[mt], sAl + off);
            }
            const int brow = ncol0 + (lane & 7);
            const int bcol = kk * 2 + ((lane >> 3) & 1);
#pragma unroll
            for (int nt = 0; nt < 4; ++nt) {
                uint32_t off = sw128((uint32_t)(brow + nt * 8) * 128u +
                                     (uint32_t)bcol * 16u);
                ldmx2(bh[nt], sBh + off);
            }
#pragma unroll
            for (int mt = 0; mt < 4; ++mt)
#pragma unroll
                for (int nt = 0; nt < 4; ++nt) {
                    hmma16816(acc[mt][nt], ah[mt], bh[nt]);
                    hmma16816(acc[mt][nt], al[mt], bh[nt]);
                }
        }
    }

#pragma unroll
    for (int mt = 0; mt < 4; ++mt) {
        int r0 = bm + mrow0 + mt * 16 + (lane >> 2);
#pragma unroll
        for (int nt = 0; nt < 4; ++nt) {
            int cc = bn + ncol0 + nt * 8 + (lane & 3) * 2;
            *(float2*)&C[(size_t)r0 * N + cc] =
                make_float2(acc[mt][nt][0], acc[mt][nt][1]);
            *(float2*)&C[(size_t)(r0 + 8) * N + cc] =
                make_float2(acc[mt][nt][2], acc[mt][nt][3]);
        }
    }
}

// ---------------------------------------------------------------------------
// RMSNorm + RoPE + bf16 hi/lo split. grid (S, 48):
// hh 0..31 = Q (norm+rope), 32..39 = K (norm+rope), 40..47 = V (split only).
// ---------------------------------------------------------------------------
__global__ void rmsrope_kernel(const float* __restrict__ qw,
                               const float* __restrict__ kw)
{
    const int s  = blockIdx.x;
    const int hh = blockIdx.y;
    const int d  = threadIdx.x;            // 0..127

    if (hh >= 40) {                        // V: split only
        int gv = hh - 40;
        float v = g_qkv[(size_t)s * QKV_N + V_OFF + gv * HDIM + d];
        __nv_bfloat16 hi = __float2bfloat16(v);
        __nv_bfloat16 lo = __float2bfloat16(v - __bfloat162float(hi));
        size_t o = ((size_t)s * NG + gv) * HDIM + d;
        g_vh[o] = hi; g_vl[o] = lo;
        return;
    }

    const bool isq = hh < NH;
    const float* src = isq ? (g_qkv + (size_t)s * QKV_N + hh * HDIM)
                           : (g_qkv + (size_t)s * QKV_N + D_MODEL + (hh - NH) * HDIM);
    float w = isq ? qw[d] : kw[d];
    float v = src[d];

    float ss = v * v;
#pragma unroll
    for (int off = 16; off; off >>= 1)
        ss += __shfl_xor_sync(0xffffffffu, ss, off);
    __shared__ float red[4];
    if ((d & 31) == 0) red[d >> 5] = ss;
    __syncthreads();
    float tot = red[0] + red[1] + red[2] + red[3];
    float rms = rsqrtf(tot * (1.0f / HDIM) + 1e-5f);
    float xn  = v * rms * w;

    int   i    = d >> 1;
    float freq = 1.0f / powf(1000000.0f, (float)(2 * i) * (1.0f / HDIM));
    float ang  = (float)s * freq;
    float c, sn;
    sincosf(ang, &sn, &c);
    float partner = __shfl_xor_sync(0xffffffffu, xn, 1);
    float out = (d & 1) ? (partner * sn + xn * c)
                        : (xn * c - partner * sn);

    __nv_bfloat16 hi = __float2bfloat16(out);
    __nv_bfloat16 lo = __float2bfloat16(out - __bfloat162float(hi));
    if (isq) {
        size_t o = ((size_t)s * NH + hh) * HDIM + d;
        g_qh[o] = hi; g_ql[o] = lo;
    } else {
        size_t o = ((size_t)s * NG + (hh - NH)) * HDIM + d;
        g_kh[o] = hi; g_kl[o] = lo;
    }
}

// ---------------------------------------------------------------------------
// Tensor-core flash attention (bf16 hi/lo split, causal, GQA).
// CTA: 128 q rows x one head; 8 warps, each owns 16 q rows.
// Per iter: 64 keys. K/V double-buffered cp.async. smem 192KB.
// ---------------------------------------------------------------------------
#define ASMEM (192 * 1024)

__global__ __launch_bounds__(256, 1)
void attn_mma()
{
    extern __shared__ __align__(1024) char smem[];
    const uint32_t sb = smem_u32(smem);
    const int tid  = threadIdx.x;
    const int wid  = tid >> 5;
    const int lane = tid & 31;
    const int h    = blockIdx.x;
    const int g    = h >> 2;
    const int qt   = gridDim.y - 1 - blockIdx.y;   // heavy tiles first
    const int qs   = qt * 128;
    const int ktmax = 2 * qt + 1;

    const uint32_t sQh = sb, sQl = sb + 32768u;

    auto stage_kv = [&](int kt, int s) {
        const int ks = kt * 64;
        const uint32_t base = sb + 65536u + (uint32_t)s * 65536u;
#pragma unroll
        for (int i = 0; i < 4; ++i) {
            int q2  = tid + i * 256;          // 0..1023
            int row = q2 >> 4, quad = q2 & 15;
            uint32_t so = swq(row, quad);
            size_t gk = ((size_t)(ks + row) * NG + g) * HDIM + quad * 8;
            cp16(base + so,          g_kh + gk);
            cp16(base + 16384u + so, g_kl + gk);
            cp16(base + 32768u + so, g_vh + gk);
            cp16(base + 49152u + so, g_vl + gk);
        }
        asm volatile("cp.async.commit_group;" ::: "memory");
    };

    // prologue: Q + KV(0) in group 0, KV(1) in group 1
#pragma unroll
    for (int i = 0; i < 8; ++i) {
        int q2  = tid + i * 256;              // 0..2047
        int row = q2 >> 4, quad = q2 & 15;
        uint32_t so = swq(row, quad);
        size_t gq = ((size_t)(qs + row) * NH + h) * HDIM + quad * 8;
        cp16(sQh + so, g_qh + gq);
        cp16(sQl + so, g_ql + gq);
    }
    stage_kv(0, 0);
    stage_kv(1, 1);

    uint32_t qfh[8][4];
    float oacc[16][4];
    float m0 = -1e30f, m1 = -1e30f, l0 = 0.0f, l1 = 0.0f;
#pragma unroll
    for (int nt = 0; nt < 16; ++nt)
#pragma unroll
        for (int e = 0; e < 4; ++e) oacc[nt][e] = 0.0f;

    const int r  = lane >> 2;
    const int cb = (lane & 3) << 1;
    const int arow = wid * 16 + (lane & 15);
    const int ksel = lane >> 4;

    for (int kt = 0; kt <= ktmax; ++kt) {
        if (kt < ktmax)
            asm volatile("cp.async.wait_group 1;" ::: "memory");
        else
            asm volatile("cp.async.wait_group 0;" ::: "memory");
        __syncthreads();

        if (kt == 0) {   // cache Q-hi fragments (Q-lo reloaded per iter)
#pragma unroll
            for (int k8 = 0; k8 < 8; ++k8)
                ldmx4(qfh[k8], sQh + swq(arow, k8 * 2 + ksel));
        }

        const uint32_t kb = sb + 65536u + (uint32_t)(kt & 1) * 65536u;
        const int ks = kt * 64;

        // ---- S = Q K^T ----
        float sacc[8][4];
#pragma unroll
        for (int nt = 0; nt < 8; ++nt)
#pragma unroll
            for (int e = 0; e < 4; ++e) sacc[nt][e] = 0.0f;

#pragma unroll
        for (int k8 = 0; k8 < 8; ++k8) {
            uint32_t qfl[4];
            ldmx4(qfl, sQl + swq(arow, k8 * 2 + ksel));
            const int brow = (lane & 7) + ((lane & 16) >> 1);
            const int bq   = k8 * 2 + ((lane >> 3) & 1);
#pragma unroll
            for (int ntp = 0; ntp < 4; ++ntp) {
                uint32_t bh[4], bl[4];
                uint32_t off = swq(ntp * 16 + brow, bq);
                ldmx4(bh, kb + off);
                ldmx4(bl, kb + 16384u + off);
                mma16816(sacc[2 * ntp],     qfh[k8], bh);
                mma16816(sacc[2 * ntp],     qfh[k8], bl);
                mma16816(sacc[2 * ntp],     qfl,     bh);
                mma16816(sacc[2 * ntp + 1], qfh[k8], bh + 2);
                mma16816(sacc[2 * ntp + 1], qfh[k8], bl + 2);
                mma16816(sacc[2 * ntp + 1], qfl,     bh + 2);
            }
        }

        // ---- scale + mask ----
        const int R0 = qs + wid * 16 + r;
        const int R1 = R0 + 8;
#pragma unroll
        for (int nt = 0; nt < 8; ++nt)
#pragma unroll
            for (int e = 0; e < 4; ++e) sacc[nt][e] *= SCALE_ATT;
        if (kt >= 2 * qt) {
#pragma unroll
            for (int nt = 0; nt < 8; ++nt) {
                int c0 = ks + nt * 8 + cb;
                if (c0     > R0) sacc[nt][0] = -1e30f;
                if (c0 + 1 > R0) sacc[nt][1] = -1e30f;
                if (c0     > R1) sacc[nt][2] = -1e30f;
                if (c0 + 1 > R1) sacc[nt][3] = -1e30f;
            }
        }

        // ---- online softmax ----
        float rm0 = -1e30f, rm1 = -1e30f;
#pragma unroll
        for (int nt = 0; nt < 8; ++nt) {
            rm0 = fmaxf(rm0, fmaxf(sacc[nt][0], sacc[nt][1]));
            rm1 = fmaxf(rm1, fmaxf(sacc[nt][2], sacc[nt][3]));
        }
        rm0 = fmaxf(rm0, __shfl_xor_sync(0xffffffffu, rm0, 1));
        rm0 = fmaxf(rm0, __shfl_xor_sync(0xffffffffu, rm0, 2));
        rm1 = fmaxf(rm1, __shfl_xor_sync(0xffffffffu, rm1, 1));
        rm1 = fmaxf(rm1, __shfl_xor_sync(0xffffffffu, rm1, 2));
        float mn0 = fmaxf(m0, rm0), mn1 = fmaxf(m1, rm1);
        float corr0 = __expf(m0 - mn0), corr1 = __expf(m1 - mn1);
        float s0 = 0.0f, s1 = 0.0f;
#pragma unroll
        for (int nt = 0; nt < 8; ++nt) {
            sacc[nt][0] = __expf(sacc[nt][0] - mn0); s0 += sacc[nt][0];
            sacc[nt][1] = __expf(sacc[nt][1] - mn0); s0 += sacc[nt][1];
            sacc[nt][2] = __expf(sacc[nt][2] - mn1); s1 += sacc[nt][2];
            sacc[nt][3] = __expf(sacc[nt][3] - mn1); s1 += sacc[nt][3];
        }
        s0 += __shfl_xor_sync(0xffffffffu, s0, 1);
        s0 += __shfl_xor_sync(0xffffffffu, s0, 2);
        s1 += __shfl_xor_sync(0xffffffffu, s1, 1);
        s1 += __shfl_xor_sync(0xffffffffu, s1, 2);
        l0 = l0 * corr0 + s0; m0 = mn0;
        l1 = l1 * corr1 + s1; m1 = mn1;
#pragma unroll
        for (int nt = 0; nt < 16; ++nt) {
            oacc[nt][0] *= corr0; oacc[nt][1] *= corr0;
            oacc[nt][2] *= corr1; oacc[nt][3] *= corr1;
        }

        // ---- pack P -> bf16 hi/lo A-fragments ----
        uint32_t ph[4][4], pl[4][4];
#pragma unroll
        for (int kv = 0; kv < 4; ++kv) {
            ph[kv][0] = packsplit(sacc[2 * kv][0],     sacc[2 * kv][1],     pl[kv][0]);
            ph[kv][1] = packsplit(sacc[2 * kv][2],     sacc[2 * kv][3],     pl[kv][1]);
            ph[kv][2] = packsplit(sacc[2 * kv + 1][0], sacc[2 * kv + 1][1], pl[kv][2]);
            ph[kv][3] = packsplit(sacc[2 * kv + 1][2], sacc[2 * kv + 1][3], pl[kv][3]);
        }

        // ---- O += P V ----
        const uint32_t vb = kb + 32768u;
        const int vrow0 = (lane & 7) + (lane & 8);
        const int vqsel = lane >> 4;
#pragma unroll
        for (int kv = 0; kv < 4; ++kv) {
#pragma unroll
            for (int ntp = 0; ntp < 8; ++ntp) {
                uint32_t vh[4], vl[4];
                uint32_t off = swq(kv * 16 + vrow0, ntp * 2 + vqsel);
                ldmx4t(vh, vb + off);
                ldmx4t(vl, vb + 16384u + off);
                mma16816(oacc[2 * ntp],     ph[kv], vh);
                mma16816(oacc[2 * ntp],     ph[kv], vl);
                mma16816(oacc[2 * ntp],     pl[kv], vh);
                mma16816(oacc[2 * ntp + 1], ph[kv], vh + 2);
                mma16816(oacc[2 * ntp + 1], ph[kv], vl + 2);
                mma16816(oacc[2 * ntp + 1], pl[kv], vh + 2);
            }
        }
        __syncthreads();
        if (kt + 2 <= ktmax) stage_kv(kt + 2, kt & 1);
    }

    // ---- epilogue: normalize, split to fp16 hi/lo for the out-projection ----
    float inv0 = 1.0f / l0, inv1 = 1.0f / l1;
    int s0r = qs + wid * 16 + r, s1r = s0r + 8;
#pragma unroll
    for (int nt = 0; nt < 16; ++nt) {
        int col = h * HDIM + nt * 8 + cb;
        uint32_t lo0, lo1;
        uint32_t hi0 = packsplit_h(oacc[nt][0] * inv0, oacc[nt][1] * inv0, lo0);
        uint32_t hi1 = packsplit_h(oacc[nt][2] * inv1, oacc[nt][3] * inv1, lo1);
        *(uint32_t*)&g_ah[(size_t)s0r * D_MODEL + col] = hi0;
        *(uint32_t*)&g_al[(size_t)s0r * D_MODEL + col] = lo0;
        *(uint32_t*)&g_ah[(size_t)s1r * D_MODEL + col] = hi1;
        *(uint32_t*)&g_al[(size_t)s1r * D_MODEL + col] = lo1;
    }
}

// ---------------------------------------------------------------------------
extern "C" void kernel_launch(void* const* d_in, const int* in_sizes, int n_in,
                              void* d_out, int out_size)
{
    const float* x     = (const float*)d_in[0];
    const float* w_qkv = (const float*)d_in[1];
    const float* w_out = (const float*)d_in[2];
    const float* q_ln  = (const float*)d_in[3];
    const float* k_ln  = (const float*)d_in[4];
    float* out = (float*)d_out;

    void *qkv_p;
    void *xh, *xl, *wqh, *woh, *ah, *al;
    cudaGetSymbolAddress(&qkv_p, g_qkv);
    cudaGetSymbolAddress(&xh, g_xh);   cudaGetSymbolAddress(&xl, g_xl);
    cudaGetSymbolAddress(&wqh, g_wqh);
    cudaGetSymbolAddress(&woh, g_woh);
    cudaGetSymbolAddress(&ah, g_ah);   cudaGetSymbolAddress(&al, g_al);

    cudaFuncSetAttribute(gemm2_mma, cudaFuncAttributeMaxDynamicSharedMemorySize,
                         GSMEM2);
    cudaFuncSetAttribute(attn_mma, cudaFuncAttributeMaxDynamicSharedMemorySize,
                         ASMEM);

    // 0) splits: x -> fp16 hi/lo; w_qkv, w_out -> fp16 round
    {
        int n4 = (S_LEN * D_MODEL) / 4;
        split_h_kernel<<<(n4 + 255) / 256, 256>>>(x, (__half*)xh, (__half*)xl, n4);
        n4 = (QKV_N * D_MODEL) / 4;
        round_h_kernel<<<(n4 + 255) / 256, 256>>>(w_qkv, (__half*)wqh, n4);
        n4 = (D_MODEL * D_MODEL) / 4;
        round_h_kernel<<<(n4 + 255) / 256, 256>>>(w_out, (__half*)woh, n4);
    }

    // 1) QKV projection (fp16 2-term)
    gemm2_mma<<<dim3(QKV_N / BN, S_LEN / BM), 256, GSMEM2>>>(
        (const __half*)xh, (const __half*)xl, (const __half*)wqh,
        (float*)qkv_p, S_LEN, QKV_N, D_MODEL);

    // 2) RMSNorm + RoPE + splits (Q, K, V)
    rmsrope_kernel<<<dim3(S_LEN, NH + 2 * NG), 128>>>(q_ln, k_ln);

    // 3) Tensor-core flash attention -> g_ah/g_al (fp16 hi/lo)
    attn_mma<<<dim3(NH, S_LEN / 128), 256, ASMEM>>>();

    // 4) Output projection (fp16 2-term)
    gemm2_mma<<<dim3(D_MODEL / BN, S_LEN / BM), 256, GSMEM2>>>(
        (const __half*)ah, (const __half*)al, (const __half*)woh,
        out, S_LEN, D_MODEL, D_MODEL);
}